// round 7
// baseline (speedup 1.0000x reference)
#include <cuda_runtime.h>
#include <cuda_bf16.h>
#include <math.h>
#include <stdint.h>

#define O_DIM 1024
#define D_DIM 1024
#define E_NUM 16
#define TOPK  4
#define H_DIM 2048
#define A_DIM 64
#define NPAIR (O_DIM * TOPK)
#define FLT_MIN_NORM 1.17549435e-38f

// ---------------- scratch (static device memory; no allocs) ----------------
__device__ int      g_topk_idx[NPAIR];
__device__ float    g_topk_gate[NPAIR];
__device__ float    g_importance[O_DIM];
__device__ float    g_load[O_DIM];
__device__ int      g_base[E_NUM + 1];
__device__ int      g_rows_sorted[NPAIR];
__device__ int      g_pair_of[NPAIR];
__device__ unsigned g_obs_hi[O_DIM * D_DIM / 2];   // bf16x2-packed obs hi
__device__ unsigned g_obs_lo[O_DIM * D_DIM / 2];   // bf16x2-packed obs lo
__device__ unsigned g_h_hi[NPAIR * H_DIM / 2];     // bf16x2 relu(fc1) hi
__device__ unsigned g_h_lo[NPAIR * H_DIM / 2];     // bf16x2 relu(fc1) lo
__device__ float    g_z[NPAIR * A_DIM];            // fc2 outputs per pair

// ---------------- helpers ----------------
__device__ __forceinline__ uint32_t smem_u32(const void* p) {
    uint32_t a;
    asm("{ .reg .u64 t; cvta.to.shared.u64 t, %1; cvt.u32.u64 %0, t; }" : "=r"(a) : "l"(p));
    return a;
}

__device__ __forceinline__ void cp_async16(uint32_t saddr, const void* gptr) {
    asm volatile("cp.async.cg.shared.global [%0], [%1], 16;" :: "r"(saddr), "l"(gptr));
}
__device__ __forceinline__ void cp_commit() {
    asm volatile("cp.async.commit_group;" ::: "memory");
}
template <int N> __device__ __forceinline__ void cp_wait() {
    asm volatile("cp.async.wait_group %0;" :: "n"(N) : "memory");
}

// split two fp32 into packed bf16x2 hi + bf16x2 lo (low half = first elem)
__device__ __forceinline__ void split2(float f0, float f1, unsigned& hi, unsigned& lo) {
    asm("cvt.rn.bf16x2.f32 %0, %1, %2;" : "=r"(hi) : "f"(f1), "f"(f0));
    float h0 = __uint_as_float(hi << 16);
    float h1 = __uint_as_float(hi & 0xFFFF0000u);
    float l0 = f0 - h0, l1 = f1 - h1;
    asm("cvt.rn.bf16x2.f32 %0, %1, %2;" : "=r"(lo) : "f"(l1), "f"(l0));
}

__device__ __forceinline__ void mma_bf16(float c[4], unsigned a0, unsigned a1,
                                         unsigned a2, unsigned a3,
                                         unsigned b0, unsigned b1) {
    asm volatile(
        "mma.sync.aligned.m16n8k16.row.col.f32.bf16.bf16.f32 "
        "{%0,%1,%2,%3}, {%4,%5,%6,%7}, {%8,%9}, {%0,%1,%2,%3};\n"
        : "+f"(c[0]), "+f"(c[1]), "+f"(c[2]), "+f"(c[3])
        : "r"(a0), "r"(a1), "r"(a2), "r"(a3), "r"(b0), "r"(b1));
}

// ---------------- K0: pre-split obs into bf16 hi/lo ----------------
__global__ __launch_bounds__(256) void prep_obs_kernel(const float* __restrict__ obs) {
    int i = blockIdx.x * blockDim.x + threadIdx.x;   // one bf16x2 pair
    if (i >= O_DIM * D_DIM / 2) return;
    float2 f = reinterpret_cast<const float2*>(obs)[i];
    unsigned hi, lo;
    split2(f.x, f.y, hi, lo);
    g_obs_hi[i] = hi;
    g_obs_lo[i] = lo;
}

// ---------------- K1: gating ----------------
__global__ __launch_bounds__(256) void gate_kernel(const float* __restrict__ obs,
                                                   const float* __restrict__ wg) {
    int o = blockIdx.x;
    int tid = threadIdx.x;
    const float* wrow = wg + (size_t)o * D_DIM * E_NUM;
    const float* orow = obs + (size_t)o * D_DIM;

    float acc[E_NUM];
#pragma unroll
    for (int i = 0; i < E_NUM; i++) acc[i] = 0.f;

    for (int d = tid; d < D_DIM; d += 256) {
        float x = orow[d];
        const float4* p = reinterpret_cast<const float4*>(wrow + (size_t)d * E_NUM);
        float4 v0 = p[0], v1 = p[1], v2 = p[2], v3 = p[3];
        acc[0]  += x * v0.x; acc[1]  += x * v0.y; acc[2]  += x * v0.z; acc[3]  += x * v0.w;
        acc[4]  += x * v1.x; acc[5]  += x * v1.y; acc[6]  += x * v1.z; acc[7]  += x * v1.w;
        acc[8]  += x * v2.x; acc[9]  += x * v2.y; acc[10] += x * v2.z; acc[11] += x * v2.w;
        acc[12] += x * v3.x; acc[13] += x * v3.y; acc[14] += x * v3.z; acc[15] += x * v3.w;
    }
#pragma unroll
    for (int i = 0; i < E_NUM; i++) {
#pragma unroll
        for (int off = 16; off; off >>= 1)
            acc[i] += __shfl_xor_sync(0xffffffffu, acc[i], off);
    }
    __shared__ float s[8][E_NUM];
    int warp = tid >> 5, lane = tid & 31;
    if (lane == 0) {
#pragma unroll
        for (int i = 0; i < E_NUM; i++) s[warp][i] = acc[i];
    }
    __syncthreads();
    if (tid == 0) {
        float logit[E_NUM];
        for (int e = 0; e < E_NUM; e++) {
            float t = 0.f;
            for (int w = 0; w < 8; w++) t += s[w][e];
            logit[e] = t;
        }
        bool taken[E_NUM];
        for (int e = 0; e < E_NUM; e++) taken[e] = false;
        int idx[TOPK]; float val[TOPK];
        for (int k = 0; k < TOPK; k++) {
            float best = -3.4e38f; int bi = 0;
            for (int e = 0; e < E_NUM; e++)
                if (!taken[e] && logit[e] > best) { best = logit[e]; bi = e; }
            taken[bi] = true; idx[k] = bi; val[k] = best;
        }
        float m = val[0];
        float ex[TOPK]; float se = 0.f;
        for (int k = 0; k < TOPK; k++) { ex[k] = expf(val[k] - m); se += ex[k]; }
        float gates[E_NUM];
        for (int e = 0; e < E_NUM; e++) gates[e] = 0.f;
        for (int k = 0; k < TOPK; k++) gates[idx[k]] = ex[k] / se;
        float imp = 0.f; int ldc = 0;
        for (int e = 0; e < E_NUM; e++) { imp += gates[e]; ldc += (gates[e] > 0.f); }
        for (int k = 0; k < TOPK; k++) {
            g_topk_idx[o * TOPK + k]  = idx[k];
            g_topk_gate[o * TOPK + k] = gates[idx[k]];
        }
        g_importance[o] = imp;
        g_load[o] = (float)ldc;
    }
}

// ---------------- K2: deterministic binning ----------------
__global__ __launch_bounds__(512) void bin_kernel() {
    int tid = threadIdx.x;
    int warp = tid >> 5, lane = tid & 31;
    int e = warp;
    __shared__ int scnt[E_NUM];
    __shared__ int sbase[E_NUM + 1];

    int cnt = 0;
    for (int base = 0; base < O_DIM; base += 32) {
        int r = base + lane;
        bool f = (g_topk_idx[r * 4 + 0] == e) || (g_topk_idx[r * 4 + 1] == e) ||
                 (g_topk_idx[r * 4 + 2] == e) || (g_topk_idx[r * 4 + 3] == e);
        unsigned m = __ballot_sync(0xffffffffu, f);
        cnt += __popc(m);
    }
    if (lane == 0) scnt[e] = cnt;
    __syncthreads();
    if (tid == 0) {
        int s = 0;
        for (int q = 0; q < E_NUM; q++) { sbase[q] = s; s += scnt[q]; }
        sbase[E_NUM] = s;
    }
    __syncthreads();
    if (tid < E_NUM + 1) g_base[tid] = sbase[tid];

    int off = sbase[e];
    for (int base = 0; base < O_DIM; base += 32) {
        int r = base + lane;
        int j = -1;
        if      (g_topk_idx[r * 4 + 0] == e) j = 0;
        else if (g_topk_idx[r * 4 + 1] == e) j = 1;
        else if (g_topk_idx[r * 4 + 2] == e) j = 2;
        else if (g_topk_idx[r * 4 + 3] == e) j = 3;
        bool f = (j >= 0);
        unsigned m = __ballot_sync(0xffffffffu, f);
        int pos = off + __popc(m & ((1u << lane) - 1u));
        if (f) {
            g_rows_sorted[pos] = r;
            g_pair_of[r * 4 + j] = pos;
        }
        off += __popc(m);
    }
}

// ---------------- K3: loss (two-pass variance, ddof=1) ----------------
__global__ __launch_bounds__(1024) void loss_kernel(float* __restrict__ out) {
    int tid = threadIdx.x;
    __shared__ float sh[32];
    __shared__ float bc;
    float imp = g_importance[tid];
    float ld  = g_load[tid];

    auto reduceSum = [&](float v) -> float {
#pragma unroll
        for (int o2 = 16; o2; o2 >>= 1) v += __shfl_xor_sync(0xffffffffu, v, o2);
        if ((tid & 31) == 0) sh[tid >> 5] = v;
        __syncthreads();
        if (tid < 32) {
            float r = sh[tid];
#pragma unroll
            for (int o2 = 16; o2; o2 >>= 1) r += __shfl_xor_sync(0xffffffffu, r, o2);
            if (tid == 0) bc = r;
        }
        __syncthreads();
        float r = bc;
        __syncthreads();
        return r;
    };

    float si  = reduceSum(imp);
    float mi  = si / (float)O_DIM;
    float di  = imp - mi;
    float ssi = reduceSum(di * di);
    float sl  = reduceSum(ld);
    float ml  = sl / (float)O_DIM;
    float dl  = ld - ml;
    float ssl = reduceSum(dl * dl);
    if (tid == 0) {
        float vi = ssi / (float)(O_DIM - 1);
        float vl = ssl / (float)(O_DIM - 1);
        float loss = (vi / (mi * mi + 1e-10f) + vl / (ml * ml + 1e-10f)) * 0.01f;
        out[3 * O_DIM * A_DIM] = loss;
    }
}

// ---------------- K4: action head (float4 streaming; FTZ-emulated tail) ----
__global__ __launch_bounds__(512) void action_kernel(const float* __restrict__ obs,
                                                     const float* __restrict__ lastw,
                                                     const float* __restrict__ lastb,
                                                     float* __restrict__ out) {
    int o = blockIdx.x;
    int tid = threadIdx.x;
    int a4 = (tid & 15) * 4;
    int chunk = tid >> 4;

    __shared__ float obsS[D_DIM];
    obsS[tid]       = obs[(size_t)o * D_DIM + tid];
    obsS[tid + 512] = obs[(size_t)o * D_DIM + tid + 512];
    __syncthreads();

    const float* lw = lastw + (size_t)o * D_DIM * A_DIM + (size_t)chunk * 32 * A_DIM + a4;
    float ax = 0.f, ay = 0.f, az = 0.f, aw = 0.f;
#pragma unroll 8
    for (int d = 0; d < 32; d++) {
        float4 w = *reinterpret_cast<const float4*>(lw + (size_t)d * A_DIM);
        float x = obsS[chunk * 32 + d];
        ax += x * w.x; ay += x * w.y; az += x * w.z; aw += x * w.w;
    }

    __shared__ float red[32][A_DIM];
    red[chunk][a4 + 0] = ax;
    red[chunk][a4 + 1] = ay;
    red[chunk][a4 + 2] = az;
    red[chunk][a4 + 3] = aw;
    __syncthreads();

    __shared__ float muS[A_DIM];
    __shared__ float eS[A_DIM];
    if (tid < A_DIM) {
        float m = 0.f;
        for (int c = 0; c < 32; c++) m += red[c][tid];
        muS[tid] = m + lastb[o * A_DIM + tid];
    }
    __syncthreads();
    if (tid < A_DIM) {
        float mx = muS[0];
        for (int i = 1; i < A_DIM; i++) mx = fmaxf(mx, muS[i]);
        float t  = muS[tid] - mx;
        float ef = expf(t);
        if (ef < FLT_MIN_NORM) ef = 0.f;          // FTZ: flush denormal exp result
        eS[tid] = ef;
    }
    __syncthreads();
    if (tid < A_DIM) {
        float ssum = 0.f;
        for (int i = 0; i < A_DIM; i++) ssum += eS[i];
        float p = eS[tid] / ssum;
        if (p < FLT_MIN_NORM) p = 0.f;            // FTZ: flush denormal quotient
        out[(size_t)o * A_DIM + tid] = p;
        float lp = (p == 0.f) ? logf(1e-8f) : logf(p);
        out[(size_t)O_DIM * A_DIM + o * A_DIM + tid] = lp;
    }
}

// ---------------- K5: fc1 grouped GEMM, bf16x3 split-precision --------------
// CTA 128M x 128N, 8 warps (2x4), warp tile 64x32. K-chunk 32, 2-stage cp.async.
// A: pre-split obs hi/lo bf16 (direct fragment LDS). B: w1 fp32, split at
// fragment load. D = Ahi*Bhi + Alo*Bhi + Ahi*Blo (drops lolo, err ~2^-18).
// smem stage: A_hi 128x(32bf16,pad->80B)=10240, A_lo 10240, B 32x(132f)=16896.
#define FC1_STAGE   37376
#define FC1_ROWOFF  (2 * FC1_STAGE)                 // 74752
#define FC1_SMEM    (FC1_ROWOFF + 512)              // + rowid[128]

__global__ __launch_bounds__(256, 2) void expert_fc1_kernel(const float* __restrict__ w1,
                                                            const float* __restrict__ b1) {
    int e = blockIdx.z, mt = blockIdx.y, nt = blockIdx.x;
    int pb = g_base[e];
    int ne = g_base[e + 1] - pb;
    int m0 = mt * 128;
    if (m0 >= ne) return;

    extern __shared__ char smem[];
    uint32_t sb = smem_u32(smem);
    int tid = threadIdx.x;
    int lane = tid & 31, warp = tid >> 5;
    int wm = warp >> 2, wn = warp & 3;

    int* rowid = (int*)(smem + FC1_ROWOFF);
    if (tid < 128) {
        int mi = m0 + tid;
        rowid[tid] = g_rows_sorted[pb + (mi < ne ? mi : ne - 1)];
    }
    __syncthreads();

    // cp.async coordinates
    int ar0 = tid >> 2, as0 = tid & 3;              // A slot 0: row, 16B-seg
    int ar1 = (tid + 256) >> 2, as1 = (tid + 256) & 3;
    const char* ahp0 = (const char*)g_obs_hi + (size_t)rowid[ar0] * 2048 + as0 * 16;
    const char* ahp1 = (const char*)g_obs_hi + (size_t)rowid[ar1] * 2048 + as1 * 16;
    const char* alp0 = (const char*)g_obs_lo + (size_t)rowid[ar0] * 2048 + as0 * 16;
    const char* alp1 = (const char*)g_obs_lo + (size_t)rowid[ar1] * 2048 + as1 * 16;
    int bk = tid >> 3, bns = tid & 7;               // B: k-row, 64B-seg
    const float* bptr = w1 + (size_t)e * D_DIM * H_DIM + (size_t)nt * 128 +
                        (size_t)bk * H_DIM + bns * 16;

    auto issue = [&](int st, int ch) {
        uint32_t s0 = sb + st * FC1_STAGE;
        cp_async16(s0 + ar0 * 80 + as0 * 16, ahp0 + ch * 64);
        cp_async16(s0 + ar1 * 80 + as1 * 16, ahp1 + ch * 64);
        cp_async16(s0 + 10240 + ar0 * 80 + as0 * 16, alp0 + ch * 64);
        cp_async16(s0 + 10240 + ar1 * 80 + as1 * 16, alp1 + ch * 64);
        uint32_t sB = s0 + 20480 + bk * 528 + bns * 64;
        const float* bg = bptr + (size_t)ch * 32 * H_DIM;
#pragma unroll
        for (int q = 0; q < 4; q++) cp_async16(sB + q * 16, bg + q * 4);
        cp_commit();
    };

    float c[4][4][4];
#pragma unroll
    for (int i = 0; i < 4; i++)
#pragma unroll
        for (int j = 0; j < 4; j++)
#pragma unroll
            for (int q = 0; q < 4; q++) c[i][j][q] = 0.f;

    issue(0, 0);
    issue(1, 1);

    for (int ch = 0; ch < 32; ch++) {
        if (ch < 31) cp_wait<1>(); else cp_wait<0>();
        __syncthreads();

        const unsigned* Ah = (const unsigned*)(smem + (ch & 1) * FC1_STAGE);
        const unsigned* Al = (const unsigned*)(smem + (ch & 1) * FC1_STAGE + 10240);
        const float*    Bw = (const float*)(smem + (ch & 1) * FC1_STAGE + 20480);

#pragma unroll
        for (int s = 0; s < 2; s++) {               // two k16 steps
            int s8 = s * 8;
            unsigned ah[4][4], al[4][4];
#pragma unroll
            for (int i = 0; i < 4; i++) {
                int r0 = wm * 64 + i * 16 + (lane >> 2);
                int w0 = r0 * 20 + s8 + (lane & 3);
                ah[i][0] = Ah[w0];       ah[i][1] = Ah[w0 + 160];
                ah[i][2] = Ah[w0 + 4];   ah[i][3] = Ah[w0 + 164];
                al[i][0] = Al[w0];       al[i][1] = Al[w0 + 160];
                al[i][2] = Al[w0 + 4];   al[i][3] = Al[w0 + 164];
            }
#pragma unroll
            for (int j = 0; j < 4; j++) {
                int col = wn * 32 + j * 8 + (lane >> 2);
                int kb2 = s * 16 + 2 * (lane & 3);
                float f0 = Bw[kb2 * 132 + col];
                float f1 = Bw[(kb2 + 1) * 132 + col];
                unsigned bh0, bl0; split2(f0, f1, bh0, bl0);
                float g0 = Bw[(kb2 + 8) * 132 + col];
                float g1 = Bw[(kb2 + 9) * 132 + col];
                unsigned bh1, bl1; split2(g0, g1, bh1, bl1);
#pragma unroll
                for (int i = 0; i < 4; i++) {
                    mma_bf16(c[i][j], ah[i][0], ah[i][1], ah[i][2], ah[i][3], bh0, bh1);
                    mma_bf16(c[i][j], al[i][0], al[i][1], al[i][2], al[i][3], bh0, bh1);
                    mma_bf16(c[i][j], ah[i][0], ah[i][1], ah[i][2], ah[i][3], bl0, bl1);
                }
            }
        }

        if (ch + 2 < 32) {
            __syncthreads();                        // buffer (ch&1) free for reuse
            issue(ch & 1, ch + 2);
        }
    }

    // epilogue: bias + relu, split to bf16 hi/lo, store packed
    const float* b1e = b1 + e * H_DIM + nt * 128;
#pragma unroll
    for (int i = 0; i < 4; i++) {
        int r0 = m0 + wm * 64 + i * 16 + (lane >> 2);
#pragma unroll
        for (int j = 0; j < 4; j++) {
            int cc = wn * 32 + j * 8 + 2 * (lane & 3);
            float bv0 = b1e[cc], bv1 = b1e[cc + 1];
            if (r0 < ne) {
                float y0 = fmaxf(c[i][j][0] + bv0, 0.f);
                float y1 = fmaxf(c[i][j][1] + bv1, 0.f);
                unsigned hi, lo; split2(y0, y1, hi, lo);
                size_t w = ((size_t)(pb + r0) * H_DIM + nt * 128 + cc) >> 1;
                g_h_hi[w] = hi; g_h_lo[w] = lo;
            }
            if (r0 + 8 < ne) {
                float y0 = fmaxf(c[i][j][2] + bv0, 0.f);
                float y1 = fmaxf(c[i][j][3] + bv1, 0.f);
                unsigned hi, lo; split2(y0, y1, hi, lo);
                size_t w = ((size_t)(pb + r0 + 8) * H_DIM + nt * 128 + cc) >> 1;
                g_h_hi[w] = hi; g_h_lo[w] = lo;
            }
        }
    }
}

// ---------------- K6: fc2 grouped GEMM, bf16x3 ------------------------------
// CTA 64M x 64N, 8 warps (2x4), warp tile 32x16. K-chunk 32.
// A: g_h hi/lo bf16 via 2-stage cp.async. B: w2 fp32 LDG->split->STS [n][k].
__global__ __launch_bounds__(256) void expert_fc2_kernel(const float* __restrict__ w2) {
    int e = blockIdx.z, mt = blockIdx.y;
    int pb = g_base[e];
    int ne = g_base[e + 1] - pb;
    int m0 = mt * 64;
    if (m0 >= ne) return;

    __shared__ unsigned Ahs[2][64 * 20];            // [stage][row*20 + word]
    __shared__ unsigned Als[2][64 * 20];
    __shared__ __nv_bfloat16 Bh[64][40];            // [n][k] bf16
    __shared__ __nv_bfloat16 Bl[64][40];

    int tid = threadIdx.x;
    int lane = tid & 31, warp = tid >> 5;
    int wm = warp >> 2, wn = warp & 3;

    // A cp.async coords: 64 rows x 64B per matrix -> 256 slots, 1/thread
    int ar = tid >> 2, as = tid & 3;
    int rowc = pb + m0 + ar;
    if (rowc > NPAIR - 1) rowc = NPAIR - 1;
    const char* ahp = (const char*)g_h_hi + (size_t)rowc * 4096 + as * 16;
    const char* alp = (const char*)g_h_lo + (size_t)rowc * 4096 + as * 16;
    uint32_t ah_s = smem_u32(&Ahs[0][0]) + ar * 80 + as * 16;
    uint32_t al_s = smem_u32(&Als[0][0]) + ar * 80 + as * 16;
    const uint32_t stg = 64 * 20 * 4;

    // B coords: 32k x 64n fp32; thread: k=tid>>3, 8 floats at n=(tid&7)*8
    int bk = tid >> 3, bn = (tid & 7) * 8;
    const float* w2e = w2 + (size_t)e * H_DIM * A_DIM + (size_t)bk * A_DIM + bn;

    auto issueA = [&](int st, int ch) {
        cp_async16(ah_s + st * stg, ahp + ch * 64);
        cp_async16(al_s + st * stg, alp + ch * 64);
        cp_commit();
    };

    float c[2][2][4];
#pragma unroll
    for (int i = 0; i < 2; i++)
#pragma unroll
        for (int j = 0; j < 2; j++)
#pragma unroll
            for (int q = 0; q < 4; q++) c[i][j][q] = 0.f;

    float4 br0 = *reinterpret_cast<const float4*>(w2e);
    float4 br1 = *reinterpret_cast<const float4*>(w2e + 4);
    issueA(0, 0);

    for (int ch = 0; ch < 64; ch++) {
        if (ch + 1 < 64) issueA((ch + 1) & 1, ch + 1);

        // store staged B (chunk ch) split to bf16 [n][k]
        {
            float bv[8] = {br0.x, br0.y, br0.z, br0.w, br1.x, br1.y, br1.z, br1.w};
#pragma unroll
            for (int q = 0; q < 8; q++) {
                __nv_bfloat16 h = __float2bfloat16(bv[q]);
                float hf = __bfloat162float(h);
                __nv_bfloat16 l = __float2bfloat16(bv[q] - hf);
                Bh[bn + q][bk] = h;
                Bl[bn + q][bk] = l;
            }
        }
        if (ch + 1 < 64) {
            const float* bg = w2e + (size_t)(ch + 1) * 32 * A_DIM;
            br0 = *reinterpret_cast<const float4*>(bg);
            br1 = *reinterpret_cast<const float4*>(bg + 4);
        }

        if (ch + 1 < 64) cp_wait<1>(); else cp_wait<0>();
        __syncthreads();

        const unsigned* Ah = Ahs[ch & 1];
        const unsigned* Al = Als[ch & 1];
        const unsigned* BhW = (const unsigned*)&Bh[0][0];
        const unsigned* BlW = (const unsigned*)&Bl[0][0];

#pragma unroll
        for (int s = 0; s < 2; s++) {
            int s8 = s * 8;
            unsigned ah[2][4], al[2][4];
#pragma unroll
            for (int i = 0; i < 2; i++) {
                int r0 = wm * 32 + i * 16 + (lane >> 2);
                int w0 = r0 * 20 + s8 + (lane & 3);
                ah[i][0] = Ah[w0];     ah[i][1] = Ah[w0 + 160];
                ah[i][2] = Ah[w0 + 4]; ah[i][3] = Ah[w0 + 164];
                al[i][0] = Al[w0];     al[i][1] = Al[w0 + 160];
                al[i][2] = Al[w0 + 4]; al[i][3] = Al[w0 + 164];
            }
#pragma unroll
            for (int j = 0; j < 2; j++) {
                int col = wn * 16 + j * 8 + (lane >> 2);
                int w0 = col * 20 + s8 + (lane & 3);
                unsigned bh0 = BhW[w0], bh1 = BhW[w0 + 4];
                unsigned bl0 = BlW[w0], bl1 = BlW[w0 + 4];
#pragma unroll
                for (int i = 0; i < 2; i++) {
                    mma_bf16(c[i][j], ah[i][0], ah[i][1], ah[i][2], ah[i][3], bh0, bh1);
                    mma_bf16(c[i][j], al[i][0], al[i][1], al[i][2], al[i][3], bh0, bh1);
                    mma_bf16(c[i][j], ah[i][0], ah[i][1], ah[i][2], ah[i][3], bl0, bl1);
                }
            }
        }
        __syncthreads();                            // done reading B before next STS
    }

#pragma unroll
    for (int i = 0; i < 2; i++) {
        int r0 = m0 + wm * 32 + i * 16 + (lane >> 2);
#pragma unroll
        for (int j = 0; j < 2; j++) {
            int c0 = wn * 16 + j * 8 + 2 * (lane & 3);
            if (r0 < ne) {
                float* dst = g_z + (size_t)(pb + r0) * A_DIM + c0;
                dst[0] = c[i][j][0];
                dst[1] = c[i][j][1];
            }
            if (r0 + 8 < ne) {
                float* dst = g_z + (size_t)(pb + r0 + 8) * A_DIM + c0;
                dst[0] = c[i][j][2];
                dst[1] = c[i][j][3];
            }
        }
    }
}

// ---------------- K7: combine ----------------
__global__ __launch_bounds__(256) void combine_kernel(const float* __restrict__ b2,
                                                      float* __restrict__ out) {
    int i = blockIdx.x * blockDim.x + threadIdx.x;
    if (i >= O_DIM * A_DIM) return;
    int o = i >> 6, a = i & 63;
    float y = 0.f;
#pragma unroll
    for (int j = 0; j < TOPK; j++) {
        int eidx = g_topk_idx[o * TOPK + j];
        float g  = g_topk_gate[o * TOPK + j];
        int p    = g_pair_of[o * TOPK + j];
        y += g * (g_z[(size_t)p * A_DIM + a] + b2[eidx * A_DIM + a]);
    }
    out[2 * O_DIM * A_DIM + i] = y;
}

// ---------------- launch ----------------------------------------------------
extern "C" void kernel_launch(void* const* d_in, const int* in_sizes, int n_in,
                              void* d_out, int out_size) {
    const float* obs   = (const float*)d_in[0];
    const float* wgate = (const float*)d_in[1];
    const float* w1    = (const float*)d_in[2];
    const float* b1    = (const float*)d_in[3];
    const float* w2    = (const float*)d_in[4];
    const float* b2    = (const float*)d_in[5];
    const float* lastw = (const float*)d_in[6];
    const float* lastb = (const float*)d_in[7];
    float* out = (float*)d_out;

    static int smem_set = 0;
    if (!smem_set) {
        cudaFuncSetAttribute(expert_fc1_kernel,
                             cudaFuncAttributeMaxDynamicSharedMemorySize, FC1_SMEM);
        smem_set = 1;
    }

    prep_obs_kernel<<<(O_DIM * D_DIM / 2 + 255) / 256, 256>>>(obs);
    gate_kernel<<<O_DIM, 256>>>(obs, wgate);
    bin_kernel<<<1, 512>>>();
    loss_kernel<<<1, 1024>>>(out);
    action_kernel<<<O_DIM, 512>>>(obs, lastw, lastb, out);
    expert_fc1_kernel<<<dim3(16, 8, 16), 256, FC1_SMEM>>>(w1, b1);
    expert_fc2_kernel<<<dim3(1, 16, 16), 256>>>(w2);
    combine_kernel<<<(O_DIM * A_DIM + 255) / 256, 256>>>(b2, out);
}

// round 8
// speedup vs baseline: 1.8230x; 1.8230x over previous
#include <cuda_runtime.h>
#include <cuda_bf16.h>
#include <math.h>
#include <stdint.h>

#define O_DIM 1024
#define D_DIM 1024
#define E_NUM 16
#define TOPK  4
#define H_DIM 2048
#define A_DIM 64
#define NPAIR (O_DIM * TOPK)
#define FLT_MIN_NORM 1.17549435e-38f

// ---------------- scratch (static device memory; no allocs) ----------------
__device__ int      g_topk_idx[NPAIR];
__device__ float    g_topk_gate[NPAIR];
__device__ float    g_importance[O_DIM];
__device__ float    g_load[O_DIM];
__device__ int      g_base[E_NUM + 1];
__device__ int      g_rows_sorted[NPAIR];
__device__ int      g_pair_of[NPAIR];
__device__ unsigned g_obs_h[O_DIM * D_DIM / 2];    // f16x2-packed obs
__device__ unsigned g_h[NPAIR * H_DIM / 2];        // f16x2-packed relu(fc1)
__device__ float    g_z[4 * NPAIR * A_DIM];        // fc2 partials (4 k-slices)

// ---------------- helpers ----------------
__device__ __forceinline__ uint32_t smem_u32(const void* p) {
    uint32_t a;
    asm("{ .reg .u64 t; cvta.to.shared.u64 t, %1; cvt.u32.u64 %0, t; }" : "=r"(a) : "l"(p));
    return a;
}

__device__ __forceinline__ void cp_async16(uint32_t saddr, const void* gptr) {
    asm volatile("cp.async.cg.shared.global [%0], [%1], 16;" :: "r"(saddr), "l"(gptr));
}
__device__ __forceinline__ void cp_commit() {
    asm volatile("cp.async.commit_group;" ::: "memory");
}
template <int N> __device__ __forceinline__ void cp_wait() {
    asm volatile("cp.async.wait_group %0;" :: "n"(N) : "memory");
}

// pack two fp32 -> f16x2 (first arg = low half)
__device__ __forceinline__ unsigned pack_f16x2(float lo, float hi) {
    unsigned u;
    asm("cvt.rn.f16x2.f32 %0, %1, %2;" : "=r"(u) : "f"(hi), "f"(lo));
    return u;
}

__device__ __forceinline__ void mma_f16(float c[4], unsigned a0, unsigned a1,
                                        unsigned a2, unsigned a3,
                                        unsigned b0, unsigned b1) {
    asm volatile(
        "mma.sync.aligned.m16n8k16.row.col.f32.f16.f16.f32 "
        "{%0,%1,%2,%3}, {%4,%5,%6,%7}, {%8,%9}, {%0,%1,%2,%3};\n"
        : "+f"(c[0]), "+f"(c[1]), "+f"(c[2]), "+f"(c[3])
        : "r"(a0), "r"(a1), "r"(a2), "r"(a3), "r"(b0), "r"(b1));
}

// ---------------- K0: pre-convert obs to packed fp16 ----------------
__global__ __launch_bounds__(256) void prep_obs_kernel(const float* __restrict__ obs) {
    int i = blockIdx.x * blockDim.x + threadIdx.x;
    if (i >= O_DIM * D_DIM / 2) return;
    float2 f = reinterpret_cast<const float2*>(obs)[i];
    g_obs_h[i] = pack_f16x2(f.x, f.y);
}

// ---------------- K1: gating ----------------
__global__ __launch_bounds__(256) void gate_kernel(const float* __restrict__ obs,
                                                   const float* __restrict__ wg) {
    int o = blockIdx.x;
    int tid = threadIdx.x;
    const float* wrow = wg + (size_t)o * D_DIM * E_NUM;
    const float* orow = obs + (size_t)o * D_DIM;

    float acc[E_NUM];
#pragma unroll
    for (int i = 0; i < E_NUM; i++) acc[i] = 0.f;

    for (int d = tid; d < D_DIM; d += 256) {
        float x = orow[d];
        const float4* p = reinterpret_cast<const float4*>(wrow + (size_t)d * E_NUM);
        float4 v0 = p[0], v1 = p[1], v2 = p[2], v3 = p[3];
        acc[0]  += x * v0.x; acc[1]  += x * v0.y; acc[2]  += x * v0.z; acc[3]  += x * v0.w;
        acc[4]  += x * v1.x; acc[5]  += x * v1.y; acc[6]  += x * v1.z; acc[7]  += x * v1.w;
        acc[8]  += x * v2.x; acc[9]  += x * v2.y; acc[10] += x * v2.z; acc[11] += x * v2.w;
        acc[12] += x * v3.x; acc[13] += x * v3.y; acc[14] += x * v3.z; acc[15] += x * v3.w;
    }
#pragma unroll
    for (int i = 0; i < E_NUM; i++) {
#pragma unroll
        for (int off = 16; off; off >>= 1)
            acc[i] += __shfl_xor_sync(0xffffffffu, acc[i], off);
    }
    __shared__ float s[8][E_NUM];
    int warp = tid >> 5, lane = tid & 31;
    if (lane == 0) {
#pragma unroll
        for (int i = 0; i < E_NUM; i++) s[warp][i] = acc[i];
    }
    __syncthreads();
    if (tid == 0) {
        float logit[E_NUM];
        for (int e = 0; e < E_NUM; e++) {
            float t = 0.f;
            for (int w = 0; w < 8; w++) t += s[w][e];
            logit[e] = t;
        }
        bool taken[E_NUM];
        for (int e = 0; e < E_NUM; e++) taken[e] = false;
        int idx[TOPK]; float val[TOPK];
        for (int k = 0; k < TOPK; k++) {
            float best = -3.4e38f; int bi = 0;
            for (int e = 0; e < E_NUM; e++)
                if (!taken[e] && logit[e] > best) { best = logit[e]; bi = e; }
            taken[bi] = true; idx[k] = bi; val[k] = best;
        }
        float m = val[0];
        float ex[TOPK]; float se = 0.f;
        for (int k = 0; k < TOPK; k++) { ex[k] = expf(val[k] - m); se += ex[k]; }
        float gates[E_NUM];
        for (int e = 0; e < E_NUM; e++) gates[e] = 0.f;
        for (int k = 0; k < TOPK; k++) gates[idx[k]] = ex[k] / se;
        float imp = 0.f; int ldc = 0;
        for (int e = 0; e < E_NUM; e++) { imp += gates[e]; ldc += (gates[e] > 0.f); }
        for (int k = 0; k < TOPK; k++) {
            g_topk_idx[o * TOPK + k]  = idx[k];
            g_topk_gate[o * TOPK + k] = gates[idx[k]];
        }
        g_importance[o] = imp;
        g_load[o] = (float)ldc;
    }
}

// ---------------- K2: deterministic binning ----------------
__global__ __launch_bounds__(512) void bin_kernel() {
    int tid = threadIdx.x;
    int warp = tid >> 5, lane = tid & 31;
    int e = warp;
    __shared__ int scnt[E_NUM];
    __shared__ int sbase[E_NUM + 1];

    int cnt = 0;
    for (int base = 0; base < O_DIM; base += 32) {
        int r = base + lane;
        bool f = (g_topk_idx[r * 4 + 0] == e) || (g_topk_idx[r * 4 + 1] == e) ||
                 (g_topk_idx[r * 4 + 2] == e) || (g_topk_idx[r * 4 + 3] == e);
        unsigned m = __ballot_sync(0xffffffffu, f);
        cnt += __popc(m);
    }
    if (lane == 0) scnt[e] = cnt;
    __syncthreads();
    if (tid == 0) {
        int s = 0;
        for (int q = 0; q < E_NUM; q++) { sbase[q] = s; s += scnt[q]; }
        sbase[E_NUM] = s;
    }
    __syncthreads();
    if (tid < E_NUM + 1) g_base[tid] = sbase[tid];

    int off = sbase[e];
    for (int base = 0; base < O_DIM; base += 32) {
        int r = base + lane;
        int j = -1;
        if      (g_topk_idx[r * 4 + 0] == e) j = 0;
        else if (g_topk_idx[r * 4 + 1] == e) j = 1;
        else if (g_topk_idx[r * 4 + 2] == e) j = 2;
        else if (g_topk_idx[r * 4 + 3] == e) j = 3;
        bool f = (j >= 0);
        unsigned m = __ballot_sync(0xffffffffu, f);
        int pos = off + __popc(m & ((1u << lane) - 1u));
        if (f) {
            g_rows_sorted[pos] = r;
            g_pair_of[r * 4 + j] = pos;
        }
        off += __popc(m);
    }
}

// ---------------- K3: loss (two-pass variance, ddof=1) ----------------
__global__ __launch_bounds__(1024) void loss_kernel(float* __restrict__ out) {
    int tid = threadIdx.x;
    __shared__ float sh[32];
    __shared__ float bc;
    float imp = g_importance[tid];
    float ld  = g_load[tid];

    auto reduceSum = [&](float v) -> float {
#pragma unroll
        for (int o2 = 16; o2; o2 >>= 1) v += __shfl_xor_sync(0xffffffffu, v, o2);
        if ((tid & 31) == 0) sh[tid >> 5] = v;
        __syncthreads();
        if (tid < 32) {
            float r = sh[tid];
#pragma unroll
            for (int o2 = 16; o2; o2 >>= 1) r += __shfl_xor_sync(0xffffffffu, r, o2);
            if (tid == 0) bc = r;
        }
        __syncthreads();
        float r = bc;
        __syncthreads();
        return r;
    };

    float si  = reduceSum(imp);
    float mi  = si / (float)O_DIM;
    float di  = imp - mi;
    float ssi = reduceSum(di * di);
    float sl  = reduceSum(ld);
    float ml  = sl / (float)O_DIM;
    float dl  = ld - ml;
    float ssl = reduceSum(dl * dl);
    if (tid == 0) {
        float vi = ssi / (float)(O_DIM - 1);
        float vl = ssl / (float)(O_DIM - 1);
        float loss = (vi / (mi * mi + 1e-10f) + vl / (ml * ml + 1e-10f)) * 0.01f;
        out[3 * O_DIM * A_DIM] = loss;
    }
}

// ---------------- K4: action head (float4 streaming; FTZ-emulated tail) ----
__global__ __launch_bounds__(512) void action_kernel(const float* __restrict__ obs,
                                                     const float* __restrict__ lastw,
                                                     const float* __restrict__ lastb,
                                                     float* __restrict__ out) {
    int o = blockIdx.x;
    int tid = threadIdx.x;
    int a4 = (tid & 15) * 4;
    int chunk = tid >> 4;

    __shared__ float obsS[D_DIM];
    obsS[tid]       = obs[(size_t)o * D_DIM + tid];
    obsS[tid + 512] = obs[(size_t)o * D_DIM + tid + 512];
    __syncthreads();

    const float* lw = lastw + (size_t)o * D_DIM * A_DIM + (size_t)chunk * 32 * A_DIM + a4;
    float ax = 0.f, ay = 0.f, az = 0.f, aw = 0.f;
#pragma unroll 8
    for (int d = 0; d < 32; d++) {
        float4 w = *reinterpret_cast<const float4*>(lw + (size_t)d * A_DIM);
        float x = obsS[chunk * 32 + d];
        ax += x * w.x; ay += x * w.y; az += x * w.z; aw += x * w.w;
    }

    __shared__ float red[32][A_DIM];
    red[chunk][a4 + 0] = ax;
    red[chunk][a4 + 1] = ay;
    red[chunk][a4 + 2] = az;
    red[chunk][a4 + 3] = aw;
    __syncthreads();

    __shared__ float muS[A_DIM];
    __shared__ float eS[A_DIM];
    if (tid < A_DIM) {
        float m = 0.f;
        for (int c = 0; c < 32; c++) m += red[c][tid];
        muS[tid] = m + lastb[o * A_DIM + tid];
    }
    __syncthreads();
    if (tid < A_DIM) {
        float mx = muS[0];
        for (int i = 1; i < A_DIM; i++) mx = fmaxf(mx, muS[i]);
        float t  = muS[tid] - mx;
        float ef = expf(t);
        if (ef < FLT_MIN_NORM) ef = 0.f;          // FTZ: flush denormal exp result
        eS[tid] = ef;
    }
    __syncthreads();
    if (tid < A_DIM) {
        float ssum = 0.f;
        for (int i = 0; i < A_DIM; i++) ssum += eS[i];
        float p = eS[tid] / ssum;
        if (p < FLT_MIN_NORM) p = 0.f;            // FTZ: flush denormal quotient
        out[(size_t)o * A_DIM + tid] = p;
        float lp = (p == 0.f) ? logf(1e-8f) : logf(p);
        out[(size_t)O_DIM * A_DIM + o * A_DIM + tid] = lp;
    }
}

// ---------------- K5: fc1 grouped GEMM, single-term fp16 --------------------
// CTA 128M x 128N, 8 warps (2x4), warp tile 64x32, m16n8k16 f16.
// K-chunk 32, 2-stage cp.async. A: prepacked f16x2 obs rows.
// B: w1 fp32 staged, packed to f16x2 at fragment load.
// A stage: 128 rows x 80B (16 words + pad 4) = 10240 B
// B stage: 32 k-rows x 132 words = 16896 B; stage = 27136 B; x2 + rowid.
#define FC1_STAGE  27136
#define FC1_ROWOFF (2 * FC1_STAGE)
#define FC1_SMEM   (FC1_ROWOFF + 512)

__global__ __launch_bounds__(256) void expert_fc1_kernel(const float* __restrict__ w1,
                                                         const float* __restrict__ b1) {
    int e = blockIdx.z, mt = blockIdx.y, nt = blockIdx.x;
    int pb = g_base[e];
    int ne = g_base[e + 1] - pb;
    int m0 = mt * 128;
    if (m0 >= ne) return;

    extern __shared__ char smem[];
    uint32_t sb = smem_u32(smem);
    int tid = threadIdx.x;
    int lane = tid & 31, warp = tid >> 5;
    int wm = warp >> 2, wn = warp & 3;

    int* rowid = (int*)(smem + FC1_ROWOFF);
    if (tid < 128) {
        int mi = m0 + tid;
        rowid[tid] = g_rows_sorted[pb + (mi < ne ? mi : ne - 1)];
    }
    __syncthreads();

    // A: 128 rows x 64B per chunk = 512 granules, 2 per thread
    int ar0 = tid >> 2, as0 = tid & 3;
    int ar1 = (tid + 256) >> 2, as1 = (tid + 256) & 3;
    const char* ap0 = (const char*)g_obs_h + (size_t)rowid[ar0] * 2048 + as0 * 16;
    const char* ap1 = (const char*)g_obs_h + (size_t)rowid[ar1] * 2048 + as1 * 16;
    // B: 32 k-rows x 512B = 1024 granules, 4 per thread
    int bk = tid >> 3, bns = tid & 7;
    const float* bptr = w1 + (size_t)e * D_DIM * H_DIM + (size_t)nt * 128 +
                        (size_t)bk * H_DIM + bns * 16;

    auto issue = [&](int st, int ch) {
        uint32_t s0 = sb + st * FC1_STAGE;
        cp_async16(s0 + ar0 * 80 + as0 * 16, ap0 + ch * 64);
        cp_async16(s0 + ar1 * 80 + as1 * 16, ap1 + ch * 64);
        uint32_t sB = s0 + 10240 + bk * 528 + bns * 64;
        const float* bg = bptr + (size_t)ch * 32 * H_DIM;
#pragma unroll
        for (int q = 0; q < 4; q++) cp_async16(sB + q * 16, bg + q * 4);
        cp_commit();
    };

    float c[4][4][4];
#pragma unroll
    for (int i = 0; i < 4; i++)
#pragma unroll
        for (int j = 0; j < 4; j++)
#pragma unroll
            for (int q = 0; q < 4; q++) c[i][j][q] = 0.f;

    issue(0, 0);
    issue(1, 1);

    for (int ch = 0; ch < 32; ch++) {
        if (ch < 31) cp_wait<1>(); else cp_wait<0>();
        __syncthreads();

        const unsigned* Aw = (const unsigned*)(smem + (ch & 1) * FC1_STAGE);
        const float*    Bw = (const float*)(smem + (ch & 1) * FC1_STAGE + 10240);

#pragma unroll
        for (int s = 0; s < 2; s++) {               // two k16 steps
            unsigned a[4][4];
#pragma unroll
            for (int i = 0; i < 4; i++) {
                int r0 = wm * 64 + i * 16 + (lane >> 2);
                int w0 = r0 * 20 + s * 8 + (lane & 3);
                a[i][0] = Aw[w0];       a[i][1] = Aw[w0 + 160];
                a[i][2] = Aw[w0 + 4];   a[i][3] = Aw[w0 + 164];
            }
#pragma unroll
            for (int j = 0; j < 4; j++) {
                int col = wn * 32 + j * 8 + (lane >> 2);
                int kb = s * 16 + 2 * (lane & 3);
                unsigned b0 = pack_f16x2(Bw[kb * 132 + col], Bw[(kb + 1) * 132 + col]);
                unsigned b1 = pack_f16x2(Bw[(kb + 8) * 132 + col], Bw[(kb + 9) * 132 + col]);
#pragma unroll
                for (int i = 0; i < 4; i++)
                    mma_f16(c[i][j], a[i][0], a[i][1], a[i][2], a[i][3], b0, b1);
            }
        }

        if (ch + 2 < 32) {
            __syncthreads();
            issue(ch & 1, ch + 2);
        }
    }

    // epilogue: bias + relu, pack to f16x2
    const float* b1e = b1 + e * H_DIM + nt * 128;
#pragma unroll
    for (int i = 0; i < 4; i++) {
        int r0 = m0 + wm * 64 + i * 16 + (lane >> 2);
#pragma unroll
        for (int j = 0; j < 4; j++) {
            int cc = wn * 32 + j * 8 + 2 * (lane & 3);
            float bv0 = b1e[cc], bv1 = b1e[cc + 1];
            if (r0 < ne) {
                float y0 = fmaxf(c[i][j][0] + bv0, 0.f);
                float y1 = fmaxf(c[i][j][1] + bv1, 0.f);
                g_h[((size_t)(pb + r0) * H_DIM + nt * 128 + cc) >> 1] = pack_f16x2(y0, y1);
            }
            if (r0 + 8 < ne) {
                float y0 = fmaxf(c[i][j][2] + bv0, 0.f);
                float y1 = fmaxf(c[i][j][3] + bv1, 0.f);
                g_h[((size_t)(pb + r0 + 8) * H_DIM + nt * 128 + cc) >> 1] = pack_f16x2(y0, y1);
            }
        }
    }
}

// ---------------- K6: fc2 grouped GEMM, single-term fp16, K-split 4 ---------
// grid (kslice=4, mt=8, e=16). CTA 64M x 64N over K=512 slice.
// 8 warps (2x4), warp tile 32x16. K-chunk 32, 2-stage cp.async.
// A stage: 64 rows x 80B = 5120 B; B stage: 32 k-rows x 68 words = 8704 B.
#define FC2_STAGE  (5120 + 8704)
#define FC2_SMEM   (2 * FC2_STAGE)

__global__ __launch_bounds__(256) void expert_fc2_kernel(const float* __restrict__ w2) {
    int ks = blockIdx.x, mt = blockIdx.y, e = blockIdx.z;
    int pb = g_base[e];
    int ne = g_base[e + 1] - pb;
    int m0 = mt * 64;
    if (m0 >= ne) return;
    int k0 = ks * 512;

    extern __shared__ char smem[];
    uint32_t sb = smem_u32(smem);
    int tid = threadIdx.x;
    int lane = tid & 31, warp = tid >> 5;
    int wm = warp >> 2, wn = warp & 3;

    // A: 64 rows x 64B per chunk = 256 granules, 1 per thread
    int ar = tid >> 2, as = tid & 3;
    int rowc = pb + m0 + ar;
    if (rowc > NPAIR - 1) rowc = NPAIR - 1;
    const char* ap = (const char*)g_h + (size_t)rowc * (H_DIM * 2) + k0 * 2 + as * 16;
    // B: 32 k-rows x 256B = 512 granules, 2 per thread
    int bk0 = tid >> 4, bs0 = tid & 15;
    int bk1 = (tid + 256) >> 4, bs1 = (tid + 256) & 15;
    const float* w2e = w2 + (size_t)e * H_DIM * A_DIM + (size_t)k0 * A_DIM;
    const float* bp0 = w2e + (size_t)bk0 * A_DIM + bs0 * 4;
    const float* bp1 = w2e + (size_t)bk1 * A_DIM + bs1 * 4;

    auto issue = [&](int st, int ch) {
        uint32_t s0 = sb + st * FC2_STAGE;
        cp_async16(s0 + ar * 80 + as * 16, ap + ch * 64);
        uint32_t sB = s0 + 5120;
        cp_async16(sB + bk0 * 272 + bs0 * 16, bp0 + (size_t)ch * 32 * A_DIM);
        cp_async16(sB + bk1 * 272 + bs1 * 16, bp1 + (size_t)ch * 32 * A_DIM);
        cp_commit();
    };

    float c[2][2][4];
#pragma unroll
    for (int i = 0; i < 2; i++)
#pragma unroll
        for (int j = 0; j < 2; j++)
#pragma unroll
            for (int q = 0; q < 4; q++) c[i][j][q] = 0.f;

    issue(0, 0);
    issue(1, 1);

    for (int ch = 0; ch < 16; ch++) {
        if (ch < 15) cp_wait<1>(); else cp_wait<0>();
        __syncthreads();

        const unsigned* Aw = (const unsigned*)(smem + (ch & 1) * FC2_STAGE);
        const float*    Bw = (const float*)(smem + (ch & 1) * FC2_STAGE + 5120);

#pragma unroll
        for (int s = 0; s < 2; s++) {
            unsigned a[2][4];
#pragma unroll
            for (int i = 0; i < 2; i++) {
                int r0 = wm * 32 + i * 16 + (lane >> 2);
                int w0 = r0 * 20 + s * 8 + (lane & 3);
                a[i][0] = Aw[w0];       a[i][1] = Aw[w0 + 160];
                a[i][2] = Aw[w0 + 4];   a[i][3] = Aw[w0 + 164];
            }
#pragma unroll
            for (int j = 0; j < 2; j++) {
                int col = wn * 16 + j * 8 + (lane >> 2);
                int kb = s * 16 + 2 * (lane & 3);
                unsigned b0 = pack_f16x2(Bw[kb * 68 + col], Bw[(kb + 1) * 68 + col]);
                unsigned b1 = pack_f16x2(Bw[(kb + 8) * 68 + col], Bw[(kb + 9) * 68 + col]);
#pragma unroll
                for (int i = 0; i < 2; i++)
                    mma_f16(c[i][j], a[i][0], a[i][1], a[i][2], a[i][3], b0, b1);
            }
        }

        if (ch + 2 < 16) {
            __syncthreads();
            issue(ch & 1, ch + 2);
        }
    }

    float* zp = g_z + (size_t)ks * NPAIR * A_DIM;
#pragma unroll
    for (int i = 0; i < 2; i++) {
        int r0 = m0 + wm * 32 + i * 16 + (lane >> 2);
#pragma unroll
        for (int j = 0; j < 2; j++) {
            int c0 = wn * 16 + j * 8 + 2 * (lane & 3);
            if (r0 < ne) {
                float* dst = zp + (size_t)(pb + r0) * A_DIM + c0;
                dst[0] = c[i][j][0];
                dst[1] = c[i][j][1];
            }
            if (r0 + 8 < ne) {
                float* dst = zp + (size_t)(pb + r0 + 8) * A_DIM + c0;
                dst[0] = c[i][j][2];
                dst[1] = c[i][j][3];
            }
        }
    }
}

// ---------------- K7: combine (sums 4 k-slice partials) ----------------
__global__ __launch_bounds__(256) void combine_kernel(const float* __restrict__ b2,
                                                      float* __restrict__ out) {
    int i = blockIdx.x * blockDim.x + threadIdx.x;
    if (i >= O_DIM * A_DIM) return;
    int o = i >> 6, a = i & 63;
    float y = 0.f;
#pragma unroll
    for (int j = 0; j < TOPK; j++) {
        int eidx = g_topk_idx[o * TOPK + j];
        float g  = g_topk_gate[o * TOPK + j];
        int p    = g_pair_of[o * TOPK + j];
        size_t base = (size_t)p * A_DIM + a;
        float z = g_z[base] + g_z[base + (size_t)NPAIR * A_DIM] +
                  g_z[base + 2 * (size_t)NPAIR * A_DIM] + g_z[base + 3 * (size_t)NPAIR * A_DIM];
        y += g * (z + b2[eidx * A_DIM + a]);
    }
    out[2 * O_DIM * A_DIM + i] = y;
}

// ---------------- launch ----------------------------------------------------
extern "C" void kernel_launch(void* const* d_in, const int* in_sizes, int n_in,
                              void* d_out, int out_size) {
    const float* obs   = (const float*)d_in[0];
    const float* wgate = (const float*)d_in[1];
    const float* w1    = (const float*)d_in[2];
    const float* b1    = (const float*)d_in[3];
    const float* w2    = (const float*)d_in[4];
    const float* b2    = (const float*)d_in[5];
    const float* lastw = (const float*)d_in[6];
    const float* lastb = (const float*)d_in[7];
    float* out = (float*)d_out;

    static int smem_set = 0;
    if (!smem_set) {
        cudaFuncSetAttribute(expert_fc1_kernel,
                             cudaFuncAttributeMaxDynamicSharedMemorySize, FC1_SMEM);
        cudaFuncSetAttribute(expert_fc2_kernel,
                             cudaFuncAttributeMaxDynamicSharedMemorySize, FC2_SMEM);
        smem_set = 1;
    }

    // order chosen so launch #4 (ncu capture slot) = fc1
    gate_kernel<<<O_DIM, 256>>>(obs, wgate);
    bin_kernel<<<1, 512>>>();
    prep_obs_kernel<<<(O_DIM * D_DIM / 2 + 255) / 256, 256>>>(obs);
    expert_fc1_kernel<<<dim3(16, 8, 16), 256, FC1_SMEM>>>(w1, b1);
    expert_fc2_kernel<<<dim3(4, 8, 16), 256, FC2_SMEM>>>(w2);
    combine_kernel<<<(O_DIM * A_DIM + 255) / 256, 256>>>(b2, out);
    loss_kernel<<<1, 1024>>>(out);
    action_kernel<<<O_DIM, 512>>>(obs, lastw, lastb, out);
}

// round 9
// speedup vs baseline: 1.8358x; 1.0071x over previous
#include <cuda_runtime.h>
#include <cuda_bf16.h>
#include <math.h>
#include <stdint.h>

#define O_DIM 1024
#define D_DIM 1024
#define E_NUM 16
#define TOPK  4
#define H_DIM 2048
#define A_DIM 64
#define NPAIR (O_DIM * TOPK)
#define FLT_MIN_NORM 1.17549435e-38f

// ---------------- scratch (static device memory; no allocs) ----------------
__device__ int      g_topk_idx[NPAIR];
__device__ float    g_topk_gate[NPAIR];
__device__ float    g_importance[O_DIM];
__device__ float    g_load[O_DIM];
__device__ int      g_base[E_NUM + 1];
__device__ int      g_rows_sorted[NPAIR];
__device__ int      g_pair_of[NPAIR];
__device__ unsigned g_obs_h[O_DIM * D_DIM / 2];        // f16x2-packed obs (pairs along d)
__device__ unsigned g_w1p[E_NUM * (D_DIM / 2) * H_DIM]; // f16x2-packed w1 (pairs along k)
__device__ unsigned g_w2p[E_NUM * (H_DIM / 2) * A_DIM]; // f16x2-packed w2 (pairs along k)
__device__ unsigned g_h[NPAIR * H_DIM / 2];            // f16x2-packed relu(fc1)
__device__ float    g_z[4 * NPAIR * A_DIM];            // fc2 partials (4 k-slices)

#define N_OBS (O_DIM * D_DIM / 2)
#define N_W1  (E_NUM * (D_DIM / 2) * H_DIM)
#define N_W2  (E_NUM * (H_DIM / 2) * A_DIM)

// ---------------- helpers ----------------
__device__ __forceinline__ uint32_t smem_u32(const void* p) {
    uint32_t a;
    asm("{ .reg .u64 t; cvta.to.shared.u64 t, %1; cvt.u32.u64 %0, t; }" : "=r"(a) : "l"(p));
    return a;
}

__device__ __forceinline__ void cp_async16(uint32_t saddr, const void* gptr) {
    asm volatile("cp.async.cg.shared.global [%0], [%1], 16;" :: "r"(saddr), "l"(gptr));
}
__device__ __forceinline__ void cp_commit() {
    asm volatile("cp.async.commit_group;" ::: "memory");
}
template <int N> __device__ __forceinline__ void cp_wait() {
    asm volatile("cp.async.wait_group %0;" :: "n"(N) : "memory");
}

__device__ __forceinline__ unsigned pack_f16x2(float lo, float hi) {
    unsigned u;
    asm("cvt.rn.f16x2.f32 %0, %1, %2;" : "=r"(u) : "f"(hi), "f"(lo));
    return u;
}

__device__ __forceinline__ void ldmatrix_x4(unsigned r[4], uint32_t saddr) {
    asm volatile("ldmatrix.sync.aligned.m8n8.x4.shared.b16 {%0,%1,%2,%3}, [%4];"
                 : "=r"(r[0]), "=r"(r[1]), "=r"(r[2]), "=r"(r[3]) : "r"(saddr));
}

__device__ __forceinline__ void mma_f16(float c[4], unsigned a0, unsigned a1,
                                        unsigned a2, unsigned a3,
                                        unsigned b0, unsigned b1) {
    asm volatile(
        "mma.sync.aligned.m16n8k16.row.col.f32.f16.f16.f32 "
        "{%0,%1,%2,%3}, {%4,%5,%6,%7}, {%8,%9}, {%0,%1,%2,%3};\n"
        : "+f"(c[0]), "+f"(c[1]), "+f"(c[2]), "+f"(c[3])
        : "r"(a0), "r"(a1), "r"(a2), "r"(a3), "r"(b0), "r"(b1));
}

// ---------------- K0: pack obs, w1, w2 into f16x2 ----------------
__global__ __launch_bounds__(256) void prep_all(const float* __restrict__ obs,
                                                const float* __restrict__ w1,
                                                const float* __restrict__ w2) {
    int idx = blockIdx.x * 256 + threadIdx.x;
    if (idx < N_OBS) {
        float2 f = reinterpret_cast<const float2*>(obs)[idx];
        g_obs_h[idx] = pack_f16x2(f.x, f.y);
    } else if (idx < N_OBS + N_W1) {
        int t = idx - N_OBS;
        int e = t >> 20;                // 512*2048 = 2^20 per expert
        int r = t & 1048575;
        int kp = r >> 11, n = r & 2047;
        const float* p = w1 + ((size_t)e << 21) + ((size_t)kp << 12) + n;
        g_w1p[t] = pack_f16x2(p[0], p[2048]);
    } else if (idx < N_OBS + N_W1 + N_W2) {
        int t = idx - (N_OBS + N_W1);
        int e = t >> 16;                // 1024*64 = 2^16 per expert
        int r = t & 65535;
        int kp = r >> 6, n = r & 63;
        const float* p = w2 + ((size_t)e << 17) + (kp << 7) + n;
        g_w2p[t] = pack_f16x2(p[0], p[64]);
    }
}

// ---------------- K1: gating ----------------
__global__ __launch_bounds__(256) void gate_kernel(const float* __restrict__ obs,
                                                   const float* __restrict__ wg) {
    int o = blockIdx.x;
    int tid = threadIdx.x;
    const float* wrow = wg + (size_t)o * D_DIM * E_NUM;
    const float* orow = obs + (size_t)o * D_DIM;

    float acc[E_NUM];
#pragma unroll
    for (int i = 0; i < E_NUM; i++) acc[i] = 0.f;

    for (int d = tid; d < D_DIM; d += 256) {
        float x = orow[d];
        const float4* p = reinterpret_cast<const float4*>(wrow + (size_t)d * E_NUM);
        float4 v0 = p[0], v1 = p[1], v2 = p[2], v3 = p[3];
        acc[0]  += x * v0.x; acc[1]  += x * v0.y; acc[2]  += x * v0.z; acc[3]  += x * v0.w;
        acc[4]  += x * v1.x; acc[5]  += x * v1.y; acc[6]  += x * v1.z; acc[7]  += x * v1.w;
        acc[8]  += x * v2.x; acc[9]  += x * v2.y; acc[10] += x * v2.z; acc[11] += x * v2.w;
        acc[12] += x * v3.x; acc[13] += x * v3.y; acc[14] += x * v3.z; acc[15] += x * v3.w;
    }
#pragma unroll
    for (int i = 0; i < E_NUM; i++) {
#pragma unroll
        for (int off = 16; off; off >>= 1)
            acc[i] += __shfl_xor_sync(0xffffffffu, acc[i], off);
    }
    __shared__ float s[8][E_NUM];
    int warp = tid >> 5, lane = tid & 31;
    if (lane == 0) {
#pragma unroll
        for (int i = 0; i < E_NUM; i++) s[warp][i] = acc[i];
    }
    __syncthreads();
    if (tid == 0) {
        float logit[E_NUM];
        for (int e = 0; e < E_NUM; e++) {
            float t = 0.f;
            for (int w = 0; w < 8; w++) t += s[w][e];
            logit[e] = t;
        }
        bool taken[E_NUM];
        for (int e = 0; e < E_NUM; e++) taken[e] = false;
        int idx[TOPK]; float val[TOPK];
        for (int k = 0; k < TOPK; k++) {
            float best = -3.4e38f; int bi = 0;
            for (int e = 0; e < E_NUM; e++)
                if (!taken[e] && logit[e] > best) { best = logit[e]; bi = e; }
            taken[bi] = true; idx[k] = bi; val[k] = best;
        }
        float m = val[0];
        float ex[TOPK]; float se = 0.f;
        for (int k = 0; k < TOPK; k++) { ex[k] = expf(val[k] - m); se += ex[k]; }
        float gates[E_NUM];
        for (int e = 0; e < E_NUM; e++) gates[e] = 0.f;
        for (int k = 0; k < TOPK; k++) gates[idx[k]] = ex[k] / se;
        float imp = 0.f; int ldc = 0;
        for (int e = 0; e < E_NUM; e++) { imp += gates[e]; ldc += (gates[e] > 0.f); }
        for (int k = 0; k < TOPK; k++) {
            g_topk_idx[o * TOPK + k]  = idx[k];
            g_topk_gate[o * TOPK + k] = gates[idx[k]];
        }
        g_importance[o] = imp;
        g_load[o] = (float)ldc;
    }
}

// ---------------- K2: deterministic binning ----------------
__global__ __launch_bounds__(512) void bin_kernel() {
    int tid = threadIdx.x;
    int warp = tid >> 5, lane = tid & 31;
    int e = warp;
    __shared__ int scnt[E_NUM];
    __shared__ int sbase[E_NUM + 1];

    int cnt = 0;
    for (int base = 0; base < O_DIM; base += 32) {
        int r = base + lane;
        bool f = (g_topk_idx[r * 4 + 0] == e) || (g_topk_idx[r * 4 + 1] == e) ||
                 (g_topk_idx[r * 4 + 2] == e) || (g_topk_idx[r * 4 + 3] == e);
        unsigned m = __ballot_sync(0xffffffffu, f);
        cnt += __popc(m);
    }
    if (lane == 0) scnt[e] = cnt;
    __syncthreads();
    if (tid == 0) {
        int s = 0;
        for (int q = 0; q < E_NUM; q++) { sbase[q] = s; s += scnt[q]; }
        sbase[E_NUM] = s;
    }
    __syncthreads();
    if (tid < E_NUM + 1) g_base[tid] = sbase[tid];

    int off = sbase[e];
    for (int base = 0; base < O_DIM; base += 32) {
        int r = base + lane;
        int j = -1;
        if      (g_topk_idx[r * 4 + 0] == e) j = 0;
        else if (g_topk_idx[r * 4 + 1] == e) j = 1;
        else if (g_topk_idx[r * 4 + 2] == e) j = 2;
        else if (g_topk_idx[r * 4 + 3] == e) j = 3;
        bool f = (j >= 0);
        unsigned m = __ballot_sync(0xffffffffu, f);
        int pos = off + __popc(m & ((1u << lane) - 1u));
        if (f) {
            g_rows_sorted[pos] = r;
            g_pair_of[r * 4 + j] = pos;
        }
        off += __popc(m);
    }
}

// ---------------- K3: loss (two-pass variance, ddof=1) ----------------
__global__ __launch_bounds__(1024) void loss_kernel(float* __restrict__ out) {
    int tid = threadIdx.x;
    __shared__ float sh[32];
    __shared__ float bc;
    float imp = g_importance[tid];
    float ld  = g_load[tid];

    auto reduceSum = [&](float v) -> float {
#pragma unroll
        for (int o2 = 16; o2; o2 >>= 1) v += __shfl_xor_sync(0xffffffffu, v, o2);
        if ((tid & 31) == 0) sh[tid >> 5] = v;
        __syncthreads();
        if (tid < 32) {
            float r = sh[tid];
#pragma unroll
            for (int o2 = 16; o2; o2 >>= 1) r += __shfl_xor_sync(0xffffffffu, r, o2);
            if (tid == 0) bc = r;
        }
        __syncthreads();
        float r = bc;
        __syncthreads();
        return r;
    };

    float si  = reduceSum(imp);
    float mi  = si / (float)O_DIM;
    float di  = imp - mi;
    float ssi = reduceSum(di * di);
    float sl  = reduceSum(ld);
    float ml  = sl / (float)O_DIM;
    float dl  = ld - ml;
    float ssl = reduceSum(dl * dl);
    if (tid == 0) {
        float vi = ssi / (float)(O_DIM - 1);
        float vl = ssl / (float)(O_DIM - 1);
        float loss = (vi / (mi * mi + 1e-10f) + vl / (ml * ml + 1e-10f)) * 0.01f;
        out[3 * O_DIM * A_DIM] = loss;
    }
}

// ---------------- K4: action head (float4 streaming; FTZ-emulated tail) ----
__global__ __launch_bounds__(512) void action_kernel(const float* __restrict__ obs,
                                                     const float* __restrict__ lastw,
                                                     const float* __restrict__ lastb,
                                                     float* __restrict__ out) {
    int o = blockIdx.x;
    int tid = threadIdx.x;
    int a4 = (tid & 15) * 4;
    int chunk = tid >> 4;

    __shared__ float obsS[D_DIM];
    obsS[tid]       = obs[(size_t)o * D_DIM + tid];
    obsS[tid + 512] = obs[(size_t)o * D_DIM + tid + 512];
    __syncthreads();

    const float* lw = lastw + (size_t)o * D_DIM * A_DIM + (size_t)chunk * 32 * A_DIM + a4;
    float ax = 0.f, ay = 0.f, az = 0.f, aw = 0.f;
#pragma unroll 8
    for (int d = 0; d < 32; d++) {
        float4 w = *reinterpret_cast<const float4*>(lw + (size_t)d * A_DIM);
        float x = obsS[chunk * 32 + d];
        ax += x * w.x; ay += x * w.y; az += x * w.z; aw += x * w.w;
    }

    __shared__ float red[32][A_DIM];
    red[chunk][a4 + 0] = ax;
    red[chunk][a4 + 1] = ay;
    red[chunk][a4 + 2] = az;
    red[chunk][a4 + 3] = aw;
    __syncthreads();

    __shared__ float muS[A_DIM];
    __shared__ float eS[A_DIM];
    if (tid < A_DIM) {
        float m = 0.f;
        for (int c = 0; c < 32; c++) m += red[c][tid];
        muS[tid] = m + lastb[o * A_DIM + tid];
    }
    __syncthreads();
    if (tid < A_DIM) {
        float mx = muS[0];
        for (int i = 1; i < A_DIM; i++) mx = fmaxf(mx, muS[i]);
        float t  = muS[tid] - mx;
        float ef = expf(t);
        if (ef < FLT_MIN_NORM) ef = 0.f;          // FTZ: flush denormal exp result
        eS[tid] = ef;
    }
    __syncthreads();
    if (tid < A_DIM) {
        float ssum = 0.f;
        for (int i = 0; i < A_DIM; i++) ssum += eS[i];
        float p = eS[tid] / ssum;
        if (p < FLT_MIN_NORM) p = 0.f;            // FTZ: flush denormal quotient
        out[(size_t)o * A_DIM + tid] = p;
        float lp = (p == 0.f) ? logf(1e-8f) : logf(p);
        out[(size_t)O_DIM * A_DIM + o * A_DIM + tid] = lp;
    }
}

// ---------------- K5: fc1 grouped GEMM (fp16, ldmatrix, packed B) ----------
// CTA 128M x 128N, 8 warps (2x4), warp tile 64x32, m16n8k16 f16.
// K-chunk 32 (16 k-pairs). 3-stage cp.async ring, one sync per chunk.
// A stage: 128 rows x 80B (16 words + 4 pad)  = 10240 B
// B stage: 16 kp-rows x 136 words (128 + 8 pad)= 8704 B  (bank-conflict-free)
#define FC1_ASTAGE 10240
#define FC1_BSTAGE 8704
#define FC1_STG    (FC1_ASTAGE + FC1_BSTAGE)     // 18944
#define FC1_SMEM   (3 * FC1_STG + 512)           // 57344

__global__ __launch_bounds__(256, 2) void expert_fc1_kernel(const float* __restrict__ b1) {
    int e = blockIdx.z, mt = blockIdx.y, nt = blockIdx.x;
    int pb = g_base[e];
    int ne = g_base[e + 1] - pb;
    int m0 = mt * 128;
    if (m0 >= ne) return;

    extern __shared__ char smem[];
    uint32_t sb = smem_u32(smem);
    int tid = threadIdx.x;
    int lane = tid & 31, warp = tid >> 5;
    int wm = warp >> 2, wn = warp & 3;

    int* rowid = (int*)(smem + 3 * FC1_STG);
    if (tid < 128) {
        int mi = m0 + tid;
        rowid[tid] = g_rows_sorted[pb + (mi < ne ? mi : ne - 1)];
    }
    __syncthreads();

    // cp.async coordinates: A 512 granules (2/thread), B 512 granules (2/thread)
    int ar0 = tid >> 2, as0 = tid & 3;
    const char* ap0 = (const char*)g_obs_h + (size_t)rowid[ar0] * 2048 + as0 * 16;
    const char* ap1 = (const char*)g_obs_h + (size_t)rowid[ar0 + 64] * 2048 + as0 * 16;
    int bkp = tid >> 5, bns = tid & 31;
    const char* bp = (const char*)g_w1p +
                     (((size_t)e << 20) + nt * 128 + bns * 4) * 4;

    auto issue = [&](int st, int ch) {
        uint32_t s0 = sb + st * FC1_STG;
        cp_async16(s0 + ar0 * 80 + as0 * 16, ap0 + ch * 64);
        cp_async16(s0 + (ar0 + 64) * 80 + as0 * 16, ap1 + ch * 64);
        uint32_t sB = s0 + FC1_ASTAGE + bns * 16;
        cp_async16(sB + bkp * 544, bp + (size_t)(ch * 16 + bkp) * 8192);
        cp_async16(sB + (bkp + 8) * 544, bp + (size_t)(ch * 16 + bkp + 8) * 8192);
        cp_commit();
    };

    float c[4][4][4];
#pragma unroll
    for (int i = 0; i < 4; i++)
#pragma unroll
        for (int j = 0; j < 4; j++)
#pragma unroll
            for (int q = 0; q < 4; q++) c[i][j][q] = 0.f;

    issue(0, 0);
    issue(1, 1);

    // per-lane ldmatrix A address (constant part)
    uint32_t aoff = (uint32_t)(wm * 64 + (lane & 15)) * 80 + (lane >> 4) * 16;
    int colb = wn * 32 + (lane >> 2);
    int krow = lane & 3;

    for (int ch = 0; ch < 32; ch++) {
        if (ch < 31) cp_wait<1>(); else cp_wait<0>();
        __syncthreads();
        if (ch + 2 < 32) issue((ch + 2) % 3, ch + 2);

        uint32_t stg = sb + (ch % 3) * FC1_STG;
        const unsigned* Bp = (const unsigned*)(smem + (ch % 3) * FC1_STG + FC1_ASTAGE);

#pragma unroll
        for (int s = 0; s < 2; s++) {
            unsigned a[4][4];
#pragma unroll
            for (int i = 0; i < 4; i++)
                ldmatrix_x4(a[i], stg + aoff + i * 1280 + s * 32);
            unsigned b[4][2];
#pragma unroll
            for (int j = 0; j < 4; j++) {
                int w0 = (s * 8 + krow) * 136 + colb + j * 8;
                b[j][0] = Bp[w0];
                b[j][1] = Bp[w0 + 544];      // +4 kp-rows
            }
#pragma unroll
            for (int i = 0; i < 4; i++)
#pragma unroll
                for (int j = 0; j < 4; j++)
                    mma_f16(c[i][j], a[i][0], a[i][1], a[i][2], a[i][3], b[j][0], b[j][1]);
        }
    }

    // epilogue: bias + relu, pack to f16x2
    const float* b1e = b1 + e * H_DIM + nt * 128;
#pragma unroll
    for (int i = 0; i < 4; i++) {
        int r0 = m0 + wm * 64 + i * 16 + (lane >> 2);
#pragma unroll
        for (int j = 0; j < 4; j++) {
            int cc = wn * 32 + j * 8 + 2 * (lane & 3);
            float bv0 = b1e[cc], bv1 = b1e[cc + 1];
            if (r0 < ne) {
                float y0 = fmaxf(c[i][j][0] + bv0, 0.f);
                float y1 = fmaxf(c[i][j][1] + bv1, 0.f);
                g_h[((size_t)(pb + r0) * H_DIM + nt * 128 + cc) >> 1] = pack_f16x2(y0, y1);
            }
            if (r0 + 8 < ne) {
                float y0 = fmaxf(c[i][j][2] + bv0, 0.f);
                float y1 = fmaxf(c[i][j][3] + bv1, 0.f);
                g_h[((size_t)(pb + r0 + 8) * H_DIM + nt * 128 + cc) >> 1] = pack_f16x2(y0, y1);
            }
        }
    }
}

// ---------------- K6: fc2 grouped GEMM (fp16, ldmatrix, packed B, K-split 4)
// grid (ks=4, mt=8, e=16). CTA 64M x 64N over K=512 slice.
// A stage: 64 rows x 80B = 5120 B; B stage: 16 kp x 72 words = 4608 B.
#define FC2_ASTAGE 5120
#define FC2_BSTAGE 4608
#define FC2_STG    (FC2_ASTAGE + FC2_BSTAGE)     // 9728
#define FC2_SMEM   (3 * FC2_STG)                 // 29184

__global__ __launch_bounds__(256) void expert_fc2_kernel() {
    int ks = blockIdx.x, mt = blockIdx.y, e = blockIdx.z;
    int pb = g_base[e];
    int ne = g_base[e + 1] - pb;
    int m0 = mt * 64;
    if (m0 >= ne) return;
    int kp0 = ks * 256;                          // 512 k = 256 k-pairs per slice

    extern __shared__ char smem[];
    uint32_t sb = smem_u32(smem);
    int tid = threadIdx.x;
    int lane = tid & 31, warp = tid >> 5;
    int wm = warp >> 2, wn = warp & 3;

    // A: 256 granules (1/thread); B: 256 granules (1/thread)
    int ar = tid >> 2, as = tid & 3;
    int rowc = pb + m0 + ar;
    if (rowc > NPAIR - 1) rowc = NPAIR - 1;
    const char* ap = (const char*)g_h + (size_t)rowc * 4096 + kp0 * 4 + as * 16;
    int bkp = tid >> 4, bns = tid & 15;
    const char* bp = (const char*)g_w2p +
                     (((size_t)e << 16) + (size_t)(kp0 + bkp) * 64 + bns * 4) * 4;

    auto issue = [&](int st, int ch) {
        uint32_t s0 = sb + st * FC2_STG;
        cp_async16(s0 + ar * 80 + as * 16, ap + ch * 64);
        cp_async16(s0 + FC2_ASTAGE + bkp * 288 + bns * 16, bp + (size_t)ch * 16 * 256);
        cp_commit();
    };

    float c[2][2][4];
#pragma unroll
    for (int i = 0; i < 2; i++)
#pragma unroll
        for (int j = 0; j < 2; j++)
#pragma unroll
            for (int q = 0; q < 4; q++) c[i][j][q] = 0.f;

    issue(0, 0);
    issue(1, 1);

    uint32_t aoff = (uint32_t)(wm * 32 + (lane & 15)) * 80 + (lane >> 4) * 16;
    int colb = wn * 16 + (lane >> 2);
    int krow = lane & 3;

    for (int ch = 0; ch < 16; ch++) {
        if (ch < 15) cp_wait<1>(); else cp_wait<0>();
        __syncthreads();
        if (ch + 2 < 16) issue((ch + 2) % 3, ch + 2);

        uint32_t stg = sb + (ch % 3) * FC2_STG;
        const unsigned* Bp = (const unsigned*)(smem + (ch % 3) * FC2_STG + FC2_ASTAGE);

#pragma unroll
        for (int s = 0; s < 2; s++) {
            unsigned a[2][4];
#pragma unroll
            for (int i = 0; i < 2; i++)
                ldmatrix_x4(a[i], stg + aoff + i * 1280 + s * 32);
            unsigned b[2][2];
#pragma unroll
            for (int j = 0; j < 2; j++) {
                int w0 = (s * 8 + krow) * 72 + colb + j * 8;
                b[j][0] = Bp[w0];
                b[j][1] = Bp[w0 + 288];      // +4 kp-rows
            }
#pragma unroll
            for (int i = 0; i < 2; i++)
#pragma unroll
                for (int j = 0; j < 2; j++)
                    mma_f16(c[i][j], a[i][0], a[i][1], a[i][2], a[i][3], b[j][0], b[j][1]);
        }
    }

    float* zp = g_z + (size_t)ks * NPAIR * A_DIM;
#pragma unroll
    for (int i = 0; i < 2; i++) {
        int r0 = m0 + wm * 32 + i * 16 + (lane >> 2);
#pragma unroll
        for (int j = 0; j < 2; j++) {
            int c0 = wn * 16 + j * 8 + 2 * (lane & 3);
            if (r0 < ne) {
                float* dst = zp + (size_t)(pb + r0) * A_DIM + c0;
                dst[0] = c[i][j][0];
                dst[1] = c[i][j][1];
            }
            if (r0 + 8 < ne) {
                float* dst = zp + (size_t)(pb + r0 + 8) * A_DIM + c0;
                dst[0] = c[i][j][2];
                dst[1] = c[i][j][3];
            }
        }
    }
}

// ---------------- K7: combine (sums 4 k-slice partials) ----------------
__global__ __launch_bounds__(256) void combine_kernel(const float* __restrict__ b2,
                                                      float* __restrict__ out) {
    int i = blockIdx.x * blockDim.x + threadIdx.x;
    if (i >= O_DIM * A_DIM) return;
    int o = i >> 6, a = i & 63;
    float y = 0.f;
#pragma unroll
    for (int j = 0; j < TOPK; j++) {
        int eidx = g_topk_idx[o * TOPK + j];
        float g  = g_topk_gate[o * TOPK + j];
        int p    = g_pair_of[o * TOPK + j];
        size_t base = (size_t)p * A_DIM + a;
        float z = g_z[base] + g_z[base + (size_t)NPAIR * A_DIM] +
                  g_z[base + 2 * (size_t)NPAIR * A_DIM] + g_z[base + 3 * (size_t)NPAIR * A_DIM];
        y += g * (z + b2[eidx * A_DIM + a]);
    }
    out[2 * O_DIM * A_DIM + i] = y;
}

// ---------------- launch ----------------------------------------------------
extern "C" void kernel_launch(void* const* d_in, const int* in_sizes, int n_in,
                              void* d_out, int out_size) {
    const float* obs   = (const float*)d_in[0];
    const float* wgate = (const float*)d_in[1];
    const float* w1    = (const float*)d_in[2];
    const float* b1    = (const float*)d_in[3];
    const float* w2    = (const float*)d_in[4];
    const float* b2    = (const float*)d_in[5];
    const float* lastw = (const float*)d_in[6];
    const float* lastb = (const float*)d_in[7];
    float* out = (float*)d_out;

    static int smem_set = 0;
    if (!smem_set) {
        cudaFuncSetAttribute(expert_fc1_kernel,
                             cudaFuncAttributeMaxDynamicSharedMemorySize, FC1_SMEM);
        cudaFuncSetAttribute(expert_fc2_kernel,
                             cudaFuncAttributeMaxDynamicSharedMemorySize, FC2_SMEM);
        smem_set = 1;
    }

    int prep_blocks = (N_OBS + N_W1 + N_W2 + 255) / 256;

    // order keeps fc1 at launch slot 4 (ncu capture slot)
    gate_kernel<<<O_DIM, 256>>>(obs, wgate);
    bin_kernel<<<1, 512>>>();
    prep_all<<<prep_blocks, 256>>>(obs, w1, w2);
    expert_fc1_kernel<<<dim3(16, 8, 16), 256, FC1_SMEM>>>(b1);
    expert_fc2_kernel<<<dim3(4, 8, 16), 256, FC2_SMEM>>>();
    combine_kernel<<<(O_DIM * A_DIM + 255) / 256, 256>>>(b2, out);
    loss_kernel<<<1, 1024>>>(out);
    action_kernel<<<O_DIM, 512>>>(obs, lastw, lastb, out);
}

// round 10
// speedup vs baseline: 2.2097x; 1.2037x over previous
#include <cuda_runtime.h>
#include <cuda_bf16.h>
#include <math.h>
#include <stdint.h>

#define O_DIM 1024
#define D_DIM 1024
#define E_NUM 16
#define TOPK  4
#define H_DIM 2048
#define A_DIM 64
#define NPAIR (O_DIM * TOPK)
#define FLT_MIN_NORM 1.17549435e-38f

// ---------------- scratch (static device memory; no allocs) ----------------
__device__ int      g_topk_idx[NPAIR];
__device__ float    g_topk_gate[NPAIR];
__device__ float    g_importance[O_DIM];
__device__ float    g_load[O_DIM];
__device__ int      g_base[E_NUM + 1];
__device__ int      g_rows_sorted[NPAIR];
__device__ int      g_pair_of[NPAIR];
__device__ unsigned g_obs_h[O_DIM * D_DIM / 2];        // f16x2-packed obs (pairs along d)
__device__ unsigned g_w1p[E_NUM * (D_DIM / 2) * H_DIM]; // f16x2-packed w1 (pairs along k)
__device__ unsigned g_w2p[E_NUM * (H_DIM / 2) * A_DIM]; // f16x2-packed w2 (pairs along k)
__device__ unsigned g_h[NPAIR * H_DIM / 2];            // f16x2-packed relu(fc1)
__device__ float    g_z[4 * NPAIR * A_DIM];            // fc2 partials (4 k-slices)

#define N_OBS4 (O_DIM * D_DIM / 8)                      // 4-pair granules
#define N_W14  (E_NUM * (D_DIM / 2) * H_DIM / 4)
#define N_W24  (E_NUM * (H_DIM / 2) * A_DIM / 4)

// ---------------- helpers ----------------
__device__ __forceinline__ uint32_t smem_u32(const void* p) {
    uint32_t a;
    asm("{ .reg .u64 t; cvta.to.shared.u64 t, %1; cvt.u32.u64 %0, t; }" : "=r"(a) : "l"(p));
    return a;
}

__device__ __forceinline__ void cp_async16(uint32_t saddr, const void* gptr) {
    asm volatile("cp.async.cg.shared.global [%0], [%1], 16;" :: "r"(saddr), "l"(gptr));
}
__device__ __forceinline__ void cp_commit() {
    asm volatile("cp.async.commit_group;" ::: "memory");
}
template <int N> __device__ __forceinline__ void cp_wait() {
    asm volatile("cp.async.wait_group %0;" :: "n"(N) : "memory");
}

__device__ __forceinline__ unsigned pack_f16x2(float lo, float hi) {
    unsigned u;
    asm("cvt.rn.f16x2.f32 %0, %1, %2;" : "=r"(u) : "f"(hi), "f"(lo));
    return u;
}

__device__ __forceinline__ void ldmatrix_x4(unsigned r[4], uint32_t saddr) {
    asm volatile("ldmatrix.sync.aligned.m8n8.x4.shared.b16 {%0,%1,%2,%3}, [%4];"
                 : "=r"(r[0]), "=r"(r[1]), "=r"(r[2]), "=r"(r[3]) : "r"(saddr));
}

__device__ __forceinline__ void mma_f16(float c[4], unsigned a0, unsigned a1,
                                        unsigned a2, unsigned a3,
                                        unsigned b0, unsigned b1) {
    asm volatile(
        "mma.sync.aligned.m16n8k16.row.col.f32.f16.f16.f32 "
        "{%0,%1,%2,%3}, {%4,%5,%6,%7}, {%8,%9}, {%0,%1,%2,%3};\n"
        : "+f"(c[0]), "+f"(c[1]), "+f"(c[2]), "+f"(c[3])
        : "r"(a0), "r"(a1), "r"(a2), "r"(a3), "r"(b0), "r"(b1));
}

// ---------------- K0: pack obs, w1, w2 into f16x2 (4-wide vectorized) -------
__global__ __launch_bounds__(256) void prep_all(const float* __restrict__ obs,
                                                const float* __restrict__ w1,
                                                const float* __restrict__ w2) {
    int idx = blockIdx.x * 256 + threadIdx.x;
    if (idx < N_OBS4) {
        // 8 consecutive floats -> 4 packed pairs
        const float4* p = reinterpret_cast<const float4*>(obs) + idx * 2;
        float4 f0 = p[0], f1 = p[1];
        uint4 u;
        u.x = pack_f16x2(f0.x, f0.y);
        u.y = pack_f16x2(f0.z, f0.w);
        u.z = pack_f16x2(f1.x, f1.y);
        u.w = pack_f16x2(f1.z, f1.w);
        reinterpret_cast<uint4*>(g_obs_h)[idx] = u;
    } else if (idx < N_OBS4 + N_W14) {
        int t = idx - N_OBS4;
        int e  = t >> 18;               // 2^18 granules per expert
        int r  = t & 262143;
        int kp = r >> 9;                // 512 granules per kp-row
        int n4 = (r & 511) * 4;
        const float* p = w1 + ((size_t)e << 21) + ((size_t)kp << 12) + n4;
        float4 f0 = *reinterpret_cast<const float4*>(p);
        float4 f1 = *reinterpret_cast<const float4*>(p + 2048);
        uint4 u;
        u.x = pack_f16x2(f0.x, f1.x);
        u.y = pack_f16x2(f0.y, f1.y);
        u.z = pack_f16x2(f0.z, f1.z);
        u.w = pack_f16x2(f0.w, f1.w);
        *reinterpret_cast<uint4*>(g_w1p + ((size_t)e << 20) + (kp << 11) + n4) = u;
    } else if (idx < N_OBS4 + N_W14 + N_W24) {
        int t = idx - (N_OBS4 + N_W14);
        int e  = t >> 14;               // 2^14 granules per expert
        int r  = t & 16383;
        int kp = r >> 4;                // 16 granules per kp-row
        int n4 = (r & 15) * 4;
        const float* p = w2 + ((size_t)e << 17) + (kp << 7) + n4;
        float4 f0 = *reinterpret_cast<const float4*>(p);
        float4 f1 = *reinterpret_cast<const float4*>(p + 64);
        uint4 u;
        u.x = pack_f16x2(f0.x, f1.x);
        u.y = pack_f16x2(f0.y, f1.y);
        u.z = pack_f16x2(f0.z, f1.z);
        u.w = pack_f16x2(f0.w, f1.w);
        *reinterpret_cast<uint4*>(g_w2p + ((size_t)e << 16) + (kp << 6) + n4) = u;
    }
}

// ---------------- K1: gating ----------------
__global__ __launch_bounds__(256) void gate_kernel(const float* __restrict__ obs,
                                                   const float* __restrict__ wg) {
    int o = blockIdx.x;
    int tid = threadIdx.x;
    const float* wrow = wg + (size_t)o * D_DIM * E_NUM;
    const float* orow = obs + (size_t)o * D_DIM;

    float acc[E_NUM];
#pragma unroll
    for (int i = 0; i < E_NUM; i++) acc[i] = 0.f;

    for (int d = tid; d < D_DIM; d += 256) {
        float x = orow[d];
        const float4* p = reinterpret_cast<const float4*>(wrow + (size_t)d * E_NUM);
        float4 v0 = p[0], v1 = p[1], v2 = p[2], v3 = p[3];
        acc[0]  += x * v0.x; acc[1]  += x * v0.y; acc[2]  += x * v0.z; acc[3]  += x * v0.w;
        acc[4]  += x * v1.x; acc[5]  += x * v1.y; acc[6]  += x * v1.z; acc[7]  += x * v1.w;
        acc[8]  += x * v2.x; acc[9]  += x * v2.y; acc[10] += x * v2.z; acc[11] += x * v2.w;
        acc[12] += x * v3.x; acc[13] += x * v3.y; acc[14] += x * v3.z; acc[15] += x * v3.w;
    }
#pragma unroll
    for (int i = 0; i < E_NUM; i++) {
#pragma unroll
        for (int off = 16; off; off >>= 1)
            acc[i] += __shfl_xor_sync(0xffffffffu, acc[i], off);
    }
    __shared__ float s[8][E_NUM];
    int warp = tid >> 5, lane = tid & 31;
    if (lane == 0) {
#pragma unroll
        for (int i = 0; i < E_NUM; i++) s[warp][i] = acc[i];
    }
    __syncthreads();
    if (tid == 0) {
        float logit[E_NUM];
        for (int e = 0; e < E_NUM; e++) {
            float t = 0.f;
            for (int w = 0; w < 8; w++) t += s[w][e];
            logit[e] = t;
        }
        bool taken[E_NUM];
        for (int e = 0; e < E_NUM; e++) taken[e] = false;
        int idx[TOPK]; float val[TOPK];
        for (int k = 0; k < TOPK; k++) {
            float best = -3.4e38f; int bi = 0;
            for (int e = 0; e < E_NUM; e++)
                if (!taken[e] && logit[e] > best) { best = logit[e]; bi = e; }
            taken[bi] = true; idx[k] = bi; val[k] = best;
        }
        float m = val[0];
        float ex[TOPK]; float se = 0.f;
        for (int k = 0; k < TOPK; k++) { ex[k] = expf(val[k] - m); se += ex[k]; }
        float gates[E_NUM];
        for (int e = 0; e < E_NUM; e++) gates[e] = 0.f;
        for (int k = 0; k < TOPK; k++) gates[idx[k]] = ex[k] / se;
        float imp = 0.f; int ldc = 0;
        for (int e = 0; e < E_NUM; e++) { imp += gates[e]; ldc += (gates[e] > 0.f); }
        for (int k = 0; k < TOPK; k++) {
            g_topk_idx[o * TOPK + k]  = idx[k];
            g_topk_gate[o * TOPK + k] = gates[idx[k]];
        }
        g_importance[o] = imp;
        g_load[o] = (float)ldc;
    }
}

// ---------------- K2: deterministic binning ----------------
__global__ __launch_bounds__(512) void bin_kernel() {
    int tid = threadIdx.x;
    int warp = tid >> 5, lane = tid & 31;
    int e = warp;
    __shared__ int scnt[E_NUM];
    __shared__ int sbase[E_NUM + 1];

    int cnt = 0;
    for (int base = 0; base < O_DIM; base += 32) {
        int r = base + lane;
        bool f = (g_topk_idx[r * 4 + 0] == e) || (g_topk_idx[r * 4 + 1] == e) ||
                 (g_topk_idx[r * 4 + 2] == e) || (g_topk_idx[r * 4 + 3] == e);
        unsigned m = __ballot_sync(0xffffffffu, f);
        cnt += __popc(m);
    }
    if (lane == 0) scnt[e] = cnt;
    __syncthreads();
    if (tid == 0) {
        int s = 0;
        for (int q = 0; q < E_NUM; q++) { sbase[q] = s; s += scnt[q]; }
        sbase[E_NUM] = s;
    }
    __syncthreads();
    if (tid < E_NUM + 1) g_base[tid] = sbase[tid];

    int off = sbase[e];
    for (int base = 0; base < O_DIM; base += 32) {
        int r = base + lane;
        int j = -1;
        if      (g_topk_idx[r * 4 + 0] == e) j = 0;
        else if (g_topk_idx[r * 4 + 1] == e) j = 1;
        else if (g_topk_idx[r * 4 + 2] == e) j = 2;
        else if (g_topk_idx[r * 4 + 3] == e) j = 3;
        bool f = (j >= 0);
        unsigned m = __ballot_sync(0xffffffffu, f);
        int pos = off + __popc(m & ((1u << lane) - 1u));
        if (f) {
            g_rows_sorted[pos] = r;
            g_pair_of[r * 4 + j] = pos;
        }
        off += __popc(m);
    }
}

// ---------------- K3: loss (two-pass variance, ddof=1) ----------------
__global__ __launch_bounds__(1024) void loss_kernel(float* __restrict__ out) {
    int tid = threadIdx.x;
    __shared__ float sh[32];
    __shared__ float bc;
    float imp = g_importance[tid];
    float ld  = g_load[tid];

    auto reduceSum = [&](float v) -> float {
#pragma unroll
        for (int o2 = 16; o2; o2 >>= 1) v += __shfl_xor_sync(0xffffffffu, v, o2);
        if ((tid & 31) == 0) sh[tid >> 5] = v;
        __syncthreads();
        if (tid < 32) {
            float r = sh[tid];
#pragma unroll
            for (int o2 = 16; o2; o2 >>= 1) r += __shfl_xor_sync(0xffffffffu, r, o2);
            if (tid == 0) bc = r;
        }
        __syncthreads();
        float r = bc;
        __syncthreads();
        return r;
    };

    float si  = reduceSum(imp);
    float mi  = si / (float)O_DIM;
    float di  = imp - mi;
    float ssi = reduceSum(di * di);
    float sl  = reduceSum(ld);
    float ml  = sl / (float)O_DIM;
    float dl  = ld - ml;
    float ssl = reduceSum(dl * dl);
    if (tid == 0) {
        float vi = ssi / (float)(O_DIM - 1);
        float vl = ssl / (float)(O_DIM - 1);
        float loss = (vi / (mi * mi + 1e-10f) + vl / (ml * ml + 1e-10f)) * 0.01f;
        out[3 * O_DIM * A_DIM] = loss;
    }
}

// ---------------- K4: action head (float4 streaming; FTZ-emulated tail) ----
__global__ __launch_bounds__(512) void action_kernel(const float* __restrict__ obs,
                                                     const float* __restrict__ lastw,
                                                     const float* __restrict__ lastb,
                                                     float* __restrict__ out) {
    int o = blockIdx.x;
    int tid = threadIdx.x;
    int a4 = (tid & 15) * 4;
    int chunk = tid >> 4;

    __shared__ float obsS[D_DIM];
    obsS[tid]       = obs[(size_t)o * D_DIM + tid];
    obsS[tid + 512] = obs[(size_t)o * D_DIM + tid + 512];
    __syncthreads();

    const float* lw = lastw + (size_t)o * D_DIM * A_DIM + (size_t)chunk * 32 * A_DIM + a4;
    float ax = 0.f, ay = 0.f, az = 0.f, aw = 0.f;
#pragma unroll 8
    for (int d = 0; d < 32; d++) {
        float4 w = *reinterpret_cast<const float4*>(lw + (size_t)d * A_DIM);
        float x = obsS[chunk * 32 + d];
        ax += x * w.x; ay += x * w.y; az += x * w.z; aw += x * w.w;
    }

    __shared__ float red[32][A_DIM];
    red[chunk][a4 + 0] = ax;
    red[chunk][a4 + 1] = ay;
    red[chunk][a4 + 2] = az;
    red[chunk][a4 + 3] = aw;
    __syncthreads();

    __shared__ float muS[A_DIM];
    __shared__ float eS[A_DIM];
    if (tid < A_DIM) {
        float m = 0.f;
        for (int c = 0; c < 32; c++) m += red[c][tid];
        muS[tid] = m + lastb[o * A_DIM + tid];
    }
    __syncthreads();
    if (tid < A_DIM) {
        float mx = muS[0];
        for (int i = 1; i < A_DIM; i++) mx = fmaxf(mx, muS[i]);
        float t  = muS[tid] - mx;
        float ef = expf(t);
        if (ef < FLT_MIN_NORM) ef = 0.f;          // FTZ: flush denormal exp result
        eS[tid] = ef;
    }
    __syncthreads();
    if (tid < A_DIM) {
        float ssum = 0.f;
        for (int i = 0; i < A_DIM; i++) ssum += eS[i];
        float p = eS[tid] / ssum;
        if (p < FLT_MIN_NORM) p = 0.f;            // FTZ: flush denormal quotient
        out[(size_t)o * A_DIM + tid] = p;
        float lp = (p == 0.f) ? logf(1e-8f) : logf(p);
        out[(size_t)O_DIM * A_DIM + o * A_DIM + tid] = lp;
    }
}

// ---------------- K5: fc1 grouped GEMM (fp16, ldmatrix, 3 CTAs/SM) ---------
// CTA 64M x 128N, 8 warps (2x4), warp tile 32x32, m16n8k16 f16.
// K-chunk 32 (16 k-pairs). 3-stage cp.async ring, one sync per chunk.
// A stage: 64 rows x 80B = 5120 B; B stage: 16 kp x 136 words = 8704 B.
#define FC1_ASTAGE 5120
#define FC1_BSTAGE 8704
#define FC1_STG    (FC1_ASTAGE + FC1_BSTAGE)     // 13824
#define FC1_SMEM   (3 * FC1_STG + 256)           // 41728

__global__ __launch_bounds__(256, 3) void expert_fc1_kernel(const float* __restrict__ b1) {
    int e = blockIdx.z, mt = blockIdx.y, nt = blockIdx.x;
    int pb = g_base[e];
    int ne = g_base[e + 1] - pb;
    int m0 = mt * 64;
    if (m0 >= ne) return;

    extern __shared__ char smem[];
    uint32_t sb = smem_u32(smem);
    int tid = threadIdx.x;
    int lane = tid & 31, warp = tid >> 5;
    int wm = warp >> 2, wn = warp & 3;

    int* rowid = (int*)(smem + 3 * FC1_STG);
    if (tid < 64) {
        int mi = m0 + tid;
        rowid[tid] = g_rows_sorted[pb + (mi < ne ? mi : ne - 1)];
    }
    __syncthreads();

    // cp.async coordinates: A 256 granules (1/thread), B 512 granules (2/thread)
    int ar0 = tid >> 2, as0 = tid & 3;
    const char* ap0 = (const char*)g_obs_h + (size_t)rowid[ar0] * 2048 + as0 * 16;
    int bkp = tid >> 5, bns = tid & 31;
    const char* bp = (const char*)g_w1p +
                     (((size_t)e << 20) + nt * 128 + bns * 4) * 4;

    auto issue = [&](int st, int ch) {
        uint32_t s0 = sb + st * FC1_STG;
        cp_async16(s0 + ar0 * 80 + as0 * 16, ap0 + ch * 64);
        uint32_t sB = s0 + FC1_ASTAGE + bns * 16;
        cp_async16(sB + bkp * 544, bp + (size_t)(ch * 16 + bkp) * 8192);
        cp_async16(sB + (bkp + 8) * 544, bp + (size_t)(ch * 16 + bkp + 8) * 8192);
        cp_commit();
    };

    float c[2][4][4];
#pragma unroll
    for (int i = 0; i < 2; i++)
#pragma unroll
        for (int j = 0; j < 4; j++)
#pragma unroll
            for (int q = 0; q < 4; q++) c[i][j][q] = 0.f;

    issue(0, 0);
    issue(1, 1);

    uint32_t aoff = (uint32_t)(wm * 32 + (lane & 15)) * 80 + (lane >> 4) * 16;
    int colb = wn * 32 + (lane >> 2);
    int krow = lane & 3;

    for (int ch = 0; ch < 32; ch++) {
        if (ch < 31) cp_wait<1>(); else cp_wait<0>();
        __syncthreads();
        if (ch + 2 < 32) issue((ch + 2) % 3, ch + 2);

        uint32_t stg = sb + (ch % 3) * FC1_STG;
        const unsigned* Bp = (const unsigned*)(smem + (ch % 3) * FC1_STG + FC1_ASTAGE);

#pragma unroll
        for (int s = 0; s < 2; s++) {
            unsigned a[2][4];
#pragma unroll
            for (int i = 0; i < 2; i++)
                ldmatrix_x4(a[i], stg + aoff + i * 1280 + s * 32);
            unsigned b[4][2];
#pragma unroll
            for (int j = 0; j < 4; j++) {
                int w0 = (s * 8 + krow) * 136 + colb + j * 8;
                b[j][0] = Bp[w0];
                b[j][1] = Bp[w0 + 544];      // +4 kp-rows
            }
#pragma unroll
            for (int i = 0; i < 2; i++)
#pragma unroll
                for (int j = 0; j < 4; j++)
                    mma_f16(c[i][j], a[i][0], a[i][1], a[i][2], a[i][3], b[j][0], b[j][1]);
        }
    }

    // epilogue: bias + relu, pack to f16x2
    const float* b1e = b1 + e * H_DIM + nt * 128;
#pragma unroll
    for (int i = 0; i < 2; i++) {
        int r0 = m0 + wm * 32 + i * 16 + (lane >> 2);
#pragma unroll
        for (int j = 0; j < 4; j++) {
            int cc = wn * 32 + j * 8 + 2 * (lane & 3);
            float bv0 = b1e[cc], bv1 = b1e[cc + 1];
            if (r0 < ne) {
                float y0 = fmaxf(c[i][j][0] + bv0, 0.f);
                float y1 = fmaxf(c[i][j][1] + bv1, 0.f);
                g_h[((size_t)(pb + r0) * H_DIM + nt * 128 + cc) >> 1] = pack_f16x2(y0, y1);
            }
            if (r0 + 8 < ne) {
                float y0 = fmaxf(c[i][j][2] + bv0, 0.f);
                float y1 = fmaxf(c[i][j][3] + bv1, 0.f);
                g_h[((size_t)(pb + r0 + 8) * H_DIM + nt * 128 + cc) >> 1] = pack_f16x2(y0, y1);
            }
        }
    }
}

// ---------------- K6: fc2 grouped GEMM (fp16, ldmatrix, packed B, K-split 4)
// grid (ks=4, mt=8, e=16). CTA 64M x 64N over K=512 slice.
// A stage: 64 rows x 80B = 5120 B; B stage: 16 kp x 72 words = 4608 B.
#define FC2_ASTAGE 5120
#define FC2_BSTAGE 4608
#define FC2_STG    (FC2_ASTAGE + FC2_BSTAGE)     // 9728
#define FC2_SMEM   (3 * FC2_STG)                 // 29184

__global__ __launch_bounds__(256) void expert_fc2_kernel() {
    int ks = blockIdx.x, mt = blockIdx.y, e = blockIdx.z;
    int pb = g_base[e];
    int ne = g_base[e + 1] - pb;
    int m0 = mt * 64;
    if (m0 >= ne) return;
    int kp0 = ks * 256;                          // 512 k = 256 k-pairs per slice

    extern __shared__ char smem[];
    uint32_t sb = smem_u32(smem);
    int tid = threadIdx.x;
    int lane = tid & 31, warp = tid >> 5;
    int wm = warp >> 2, wn = warp & 3;

    int ar = tid >> 2, as = tid & 3;
    int rowc = pb + m0 + ar;
    if (rowc > NPAIR - 1) rowc = NPAIR - 1;
    const char* ap = (const char*)g_h + (size_t)rowc * 4096 + kp0 * 4 + as * 16;
    int bkp = tid >> 4, bns = tid & 15;
    const char* bp = (const char*)g_w2p +
                     (((size_t)e << 16) + (size_t)(kp0 + bkp) * 64 + bns * 4) * 4;

    auto issue = [&](int st, int ch) {
        uint32_t s0 = sb + st * FC2_STG;
        cp_async16(s0 + ar * 80 + as * 16, ap + ch * 64);
        cp_async16(s0 + FC2_ASTAGE + bkp * 288 + bns * 16, bp + (size_t)ch * 16 * 256);
        cp_commit();
    };

    float c[2][2][4];
#pragma unroll
    for (int i = 0; i < 2; i++)
#pragma unroll
        for (int j = 0; j < 2; j++)
#pragma unroll
            for (int q = 0; q < 4; q++) c[i][j][q] = 0.f;

    issue(0, 0);
    issue(1, 1);

    uint32_t aoff = (uint32_t)(wm * 32 + (lane & 15)) * 80 + (lane >> 4) * 16;
    int colb = wn * 16 + (lane >> 2);
    int krow = lane & 3;

    for (int ch = 0; ch < 16; ch++) {
        if (ch < 15) cp_wait<1>(); else cp_wait<0>();
        __syncthreads();
        if (ch + 2 < 16) issue((ch + 2) % 3, ch + 2);

        uint32_t stg = sb + (ch % 3) * FC2_STG;
        const unsigned* Bp = (const unsigned*)(smem + (ch % 3) * FC2_STG + FC2_ASTAGE);

#pragma unroll
        for (int s = 0; s < 2; s++) {
            unsigned a[2][4];
#pragma unroll
            for (int i = 0; i < 2; i++)
                ldmatrix_x4(a[i], stg + aoff + i * 1280 + s * 32);
            unsigned b[2][2];
#pragma unroll
            for (int j = 0; j < 2; j++) {
                int w0 = (s * 8 + krow) * 72 + colb + j * 8;
                b[j][0] = Bp[w0];
                b[j][1] = Bp[w0 + 288];      // +4 kp-rows
            }
#pragma unroll
            for (int i = 0; i < 2; i++)
#pragma unroll
                for (int j = 0; j < 2; j++)
                    mma_f16(c[i][j], a[i][0], a[i][1], a[i][2], a[i][3], b[j][0], b[j][1]);
        }
    }

    float* zp = g_z + (size_t)ks * NPAIR * A_DIM;
#pragma unroll
    for (int i = 0; i < 2; i++) {
        int r0 = m0 + wm * 32 + i * 16 + (lane >> 2);
#pragma unroll
        for (int j = 0; j < 2; j++) {
            int c0 = wn * 16 + j * 8 + 2 * (lane & 3);
            if (r0 < ne) {
                float* dst = zp + (size_t)(pb + r0) * A_DIM + c0;
                dst[0] = c[i][j][0];
                dst[1] = c[i][j][1];
            }
            if (r0 + 8 < ne) {
                float* dst = zp + (size_t)(pb + r0 + 8) * A_DIM + c0;
                dst[0] = c[i][j][2];
                dst[1] = c[i][j][3];
            }
        }
    }
}

// ---------------- K7: combine (sums 4 k-slice partials) ----------------
__global__ __launch_bounds__(256) void combine_kernel(const float* __restrict__ b2,
                                                      float* __restrict__ out) {
    int i = blockIdx.x * blockDim.x + threadIdx.x;
    if (i >= O_DIM * A_DIM) return;
    int o = i >> 6, a = i & 63;
    float y = 0.f;
#pragma unroll
    for (int j = 0; j < TOPK; j++) {
        int eidx = g_topk_idx[o * TOPK + j];
        float g  = g_topk_gate[o * TOPK + j];
        int p    = g_pair_of[o * TOPK + j];
        size_t base = (size_t)p * A_DIM + a;
        float z = g_z[base] + g_z[base + (size_t)NPAIR * A_DIM] +
                  g_z[base + 2 * (size_t)NPAIR * A_DIM] + g_z[base + 3 * (size_t)NPAIR * A_DIM];
        y += g * (z + b2[eidx * A_DIM + a]);
    }
    out[2 * O_DIM * A_DIM + i] = y;
}

// ---------------- launch ----------------------------------------------------
extern "C" void kernel_launch(void* const* d_in, const int* in_sizes, int n_in,
                              void* d_out, int out_size) {
    const float* obs   = (const float*)d_in[0];
    const float* wgate = (const float*)d_in[1];
    const float* w1    = (const float*)d_in[2];
    const float* b1    = (const float*)d_in[3];
    const float* w2    = (const float*)d_in[4];
    const float* b2    = (const float*)d_in[5];
    const float* lastw = (const float*)d_in[6];
    const float* lastb = (const float*)d_in[7];
    float* out = (float*)d_out;

    static int smem_set = 0;
    if (!smem_set) {
        cudaFuncSetAttribute(expert_fc1_kernel,
                             cudaFuncAttributeMaxDynamicSharedMemorySize, FC1_SMEM);
        cudaFuncSetAttribute(expert_fc2_kernel,
                             cudaFuncAttributeMaxDynamicSharedMemorySize, FC2_SMEM);
        smem_set = 1;
    }

    int prep_blocks = (N_OBS4 + N_W14 + N_W24 + 255) / 256;

    // order keeps fc1 at launch slot 4 (ncu capture slot)
    gate_kernel<<<O_DIM, 256>>>(obs, wgate);
    bin_kernel<<<1, 512>>>();
    prep_all<<<prep_blocks, 256>>>(obs, w1, w2);
    expert_fc1_kernel<<<dim3(16, 16, 16), 256, FC1_SMEM>>>(b1);
    expert_fc2_kernel<<<dim3(4, 8, 16), 256, FC2_SMEM>>>();
    combine_kernel<<<(O_DIM * A_DIM + 255) / 256, 256>>>(b2, out);
    loss_kernel<<<1, 1024>>>(out);
    action_kernel<<<O_DIM, 512>>>(obs, lastw, lastb, out);
}

// round 11
// speedup vs baseline: 2.5523x; 1.1550x over previous
#include <cuda_runtime.h>
#include <cuda_bf16.h>
#include <math.h>
#include <stdint.h>

#define O_DIM 1024
#define D_DIM 1024
#define E_NUM 16
#define TOPK  4
#define H_DIM 2048
#define A_DIM 64
#define NPAIR (O_DIM * TOPK)
#define FLT_MIN_NORM 1.17549435e-38f

// ---------------- scratch (static device memory; no allocs) ----------------
__device__ int      g_topk_idx[NPAIR];
__device__ float    g_topk_gate[NPAIR];
__device__ float    g_importance[O_DIM];
__device__ float    g_load[O_DIM];
__device__ int      g_base[E_NUM + 1];
__device__ int      g_rows_sorted[NPAIR];
__device__ int      g_pair_of[NPAIR];
__device__ unsigned g_obs_h[O_DIM * D_DIM / 2];
__device__ unsigned g_w1p[E_NUM * (D_DIM / 2) * H_DIM];
__device__ unsigned g_w2p[E_NUM * (H_DIM / 2) * A_DIM];
__device__ unsigned g_h[NPAIR * H_DIM / 2];
__device__ float    g_z[4 * NPAIR * A_DIM];

#define N_OBS4 (O_DIM * D_DIM / 8)
#define N_W14  (E_NUM * (D_DIM / 2) * H_DIM / 4)
#define N_W24  (E_NUM * (H_DIM / 2) * A_DIM / 4)
#define PREP_BLOCKS ((N_OBS4 + N_W14 + N_W24) / 256)   // 17920

// ---------------- helpers ----------------
__device__ __forceinline__ uint32_t smem_u32(const void* p) {
    uint32_t a;
    asm("{ .reg .u64 t; cvta.to.shared.u64 t, %1; cvt.u32.u64 %0, t; }" : "=r"(a) : "l"(p));
    return a;
}
__device__ __forceinline__ void cp_async16(uint32_t saddr, const void* gptr) {
    asm volatile("cp.async.cg.shared.global [%0], [%1], 16;" :: "r"(saddr), "l"(gptr));
}
__device__ __forceinline__ void cp_commit() {
    asm volatile("cp.async.commit_group;" ::: "memory");
}
template <int N> __device__ __forceinline__ void cp_wait() {
    asm volatile("cp.async.wait_group %0;" :: "n"(N) : "memory");
}
__device__ __forceinline__ unsigned pack_f16x2(float lo, float hi) {
    unsigned u;
    asm("cvt.rn.f16x2.f32 %0, %1, %2;" : "=r"(u) : "f"(hi), "f"(lo));
    return u;
}
__device__ __forceinline__ void ldmatrix_x4(unsigned r[4], uint32_t saddr) {
    asm volatile("ldmatrix.sync.aligned.m8n8.x4.shared.b16 {%0,%1,%2,%3}, [%4];"
                 : "=r"(r[0]), "=r"(r[1]), "=r"(r[2]), "=r"(r[3]) : "r"(saddr));
}
__device__ __forceinline__ void mma_f16(float c[4], unsigned a0, unsigned a1,
                                        unsigned a2, unsigned a3,
                                        unsigned b0, unsigned b1) {
    asm volatile(
        "mma.sync.aligned.m16n8k16.row.col.f32.f16.f16.f32 "
        "{%0,%1,%2,%3}, {%4,%5,%6,%7}, {%8,%9}, {%0,%1,%2,%3};\n"
        : "+f"(c[0]), "+f"(c[1]), "+f"(c[2]), "+f"(c[3])
        : "r"(a0), "r"(a1), "r"(a2), "r"(a3), "r"(b0), "r"(b1));
}

// ============ fused kernel 1: gate (blocks 0..1023) + prep (rest) ==========
__global__ __launch_bounds__(256) void prep_gate_kernel(const float* __restrict__ obs,
                                                        const float* __restrict__ wg,
                                                        const float* __restrict__ w1,
                                                        const float* __restrict__ w2) {
    int bid = blockIdx.x;
    int tid = threadIdx.x;

    if (bid < O_DIM) {
        // ---- gate block ----
        int o = bid;
        const float* wrow = wg + (size_t)o * D_DIM * E_NUM;
        const float* orow = obs + (size_t)o * D_DIM;

        float acc[E_NUM];
#pragma unroll
        for (int i = 0; i < E_NUM; i++) acc[i] = 0.f;
        for (int d = tid; d < D_DIM; d += 256) {
            float x = orow[d];
            const float4* p = reinterpret_cast<const float4*>(wrow + (size_t)d * E_NUM);
            float4 v0 = p[0], v1 = p[1], v2 = p[2], v3 = p[3];
            acc[0]  += x * v0.x; acc[1]  += x * v0.y; acc[2]  += x * v0.z; acc[3]  += x * v0.w;
            acc[4]  += x * v1.x; acc[5]  += x * v1.y; acc[6]  += x * v1.z; acc[7]  += x * v1.w;
            acc[8]  += x * v2.x; acc[9]  += x * v2.y; acc[10] += x * v2.z; acc[11] += x * v2.w;
            acc[12] += x * v3.x; acc[13] += x * v3.y; acc[14] += x * v3.z; acc[15] += x * v3.w;
        }
#pragma unroll
        for (int i = 0; i < E_NUM; i++) {
#pragma unroll
            for (int off = 16; off; off >>= 1)
                acc[i] += __shfl_xor_sync(0xffffffffu, acc[i], off);
        }
        __shared__ float s[8][E_NUM];
        int warp = tid >> 5, lane = tid & 31;
        if (lane == 0) {
#pragma unroll
            for (int i = 0; i < E_NUM; i++) s[warp][i] = acc[i];
        }
        __syncthreads();
        if (tid == 0) {
            float logit[E_NUM];
            for (int e = 0; e < E_NUM; e++) {
                float t = 0.f;
                for (int w = 0; w < 8; w++) t += s[w][e];
                logit[e] = t;
            }
            bool taken[E_NUM];
            for (int e = 0; e < E_NUM; e++) taken[e] = false;
            int idx[TOPK]; float val[TOPK];
            for (int k = 0; k < TOPK; k++) {
                float best = -3.4e38f; int bi = 0;
                for (int e = 0; e < E_NUM; e++)
                    if (!taken[e] && logit[e] > best) { best = logit[e]; bi = e; }
                taken[bi] = true; idx[k] = bi; val[k] = best;
            }
            float m = val[0];
            float ex[TOPK]; float se = 0.f;
            for (int k = 0; k < TOPK; k++) { ex[k] = expf(val[k] - m); se += ex[k]; }
            float gates[E_NUM];
            for (int e = 0; e < E_NUM; e++) gates[e] = 0.f;
            for (int k = 0; k < TOPK; k++) gates[idx[k]] = ex[k] / se;
            float imp = 0.f; int ldc = 0;
            for (int e = 0; e < E_NUM; e++) { imp += gates[e]; ldc += (gates[e] > 0.f); }
            for (int k = 0; k < TOPK; k++) {
                g_topk_idx[o * TOPK + k]  = idx[k];
                g_topk_gate[o * TOPK + k] = gates[idx[k]];
            }
            g_importance[o] = imp;
            g_load[o] = (float)ldc;
        }
        return;
    }

    // ---- prep block ----
    int idx = (bid - O_DIM) * 256 + tid;
    if (idx < N_OBS4) {
        const float4* p = reinterpret_cast<const float4*>(obs) + idx * 2;
        float4 f0 = p[0], f1 = p[1];
        uint4 u;
        u.x = pack_f16x2(f0.x, f0.y);
        u.y = pack_f16x2(f0.z, f0.w);
        u.z = pack_f16x2(f1.x, f1.y);
        u.w = pack_f16x2(f1.z, f1.w);
        reinterpret_cast<uint4*>(g_obs_h)[idx] = u;
    } else if (idx < N_OBS4 + N_W14) {
        int t = idx - N_OBS4;
        int e  = t >> 18;
        int r  = t & 262143;
        int kp = r >> 9;
        int n4 = (r & 511) * 4;
        const float* p = w1 + ((size_t)e << 21) + ((size_t)kp << 12) + n4;
        float4 f0 = *reinterpret_cast<const float4*>(p);
        float4 f1 = *reinterpret_cast<const float4*>(p + 2048);
        uint4 u;
        u.x = pack_f16x2(f0.x, f1.x);
        u.y = pack_f16x2(f0.y, f1.y);
        u.z = pack_f16x2(f0.z, f1.z);
        u.w = pack_f16x2(f0.w, f1.w);
        *reinterpret_cast<uint4*>(g_w1p + ((size_t)e << 20) + (kp << 11) + n4) = u;
    } else if (idx < N_OBS4 + N_W14 + N_W24) {
        int t = idx - (N_OBS4 + N_W14);
        int e  = t >> 14;
        int r  = t & 16383;
        int kp = r >> 4;
        int n4 = (r & 15) * 4;
        const float* p = w2 + ((size_t)e << 17) + (kp << 7) + n4;
        float4 f0 = *reinterpret_cast<const float4*>(p);
        float4 f1 = *reinterpret_cast<const float4*>(p + 64);
        uint4 u;
        u.x = pack_f16x2(f0.x, f1.x);
        u.y = pack_f16x2(f0.y, f1.y);
        u.z = pack_f16x2(f0.z, f1.z);
        u.w = pack_f16x2(f0.w, f1.w);
        *reinterpret_cast<uint4*>(g_w2p + ((size_t)e << 16) + (kp << 6) + n4) = u;
    }
}

// ---------------- K2: deterministic binning ----------------
__global__ __launch_bounds__(512) void bin_kernel() {
    int tid = threadIdx.x;
    int warp = tid >> 5, lane = tid & 31;
    int e = warp;
    __shared__ int scnt[E_NUM];
    __shared__ int sbase[E_NUM + 1];

    int cnt = 0;
    for (int base = 0; base < O_DIM; base += 32) {
        int r = base + lane;
        bool f = (g_topk_idx[r * 4 + 0] == e) || (g_topk_idx[r * 4 + 1] == e) ||
                 (g_topk_idx[r * 4 + 2] == e) || (g_topk_idx[r * 4 + 3] == e);
        unsigned m = __ballot_sync(0xffffffffu, f);
        cnt += __popc(m);
    }
    if (lane == 0) scnt[e] = cnt;
    __syncthreads();
    if (tid == 0) {
        int s = 0;
        for (int q = 0; q < E_NUM; q++) { sbase[q] = s; s += scnt[q]; }
        sbase[E_NUM] = s;
    }
    __syncthreads();
    if (tid < E_NUM + 1) g_base[tid] = sbase[tid];

    int off = sbase[e];
    for (int base = 0; base < O_DIM; base += 32) {
        int r = base + lane;
        int j = -1;
        if      (g_topk_idx[r * 4 + 0] == e) j = 0;
        else if (g_topk_idx[r * 4 + 1] == e) j = 1;
        else if (g_topk_idx[r * 4 + 2] == e) j = 2;
        else if (g_topk_idx[r * 4 + 3] == e) j = 3;
        bool f = (j >= 0);
        unsigned m = __ballot_sync(0xffffffffu, f);
        int pos = off + __popc(m & ((1u << lane) - 1u));
        if (f) {
            g_rows_sorted[pos] = r;
            g_pair_of[r * 4 + j] = pos;
        }
        off += __popc(m);
    }
}

// ============ fused kernel 2: fc1 + action + loss in one grid ==============
// grid = 5121 blocks, 256 threads, 41.7KB dynamic smem.
//   bid == 5120      -> loss block
//   bid % 5 == 0     -> action block (aid = bid/5, 1024 blocks)
//   else             -> fc1 block    (fid = bid - bid/5 - 1, 4096 blocks)
#define FC1_ASTAGE 5120
#define FC1_BSTAGE 8704
#define FC1_STG    (FC1_ASTAGE + FC1_BSTAGE)     // 13824
#define FC1_SMEM   (3 * FC1_STG + 256)           // 41728
#define MEGA_GRID  (5121)

__device__ __forceinline__ void fc1_body(int fid, const float* __restrict__ b1,
                                         char* smem) {
    int nt = fid & 15, mt = (fid >> 4) & 15, e = fid >> 8;
    int pb = g_base[e];
    int ne = g_base[e + 1] - pb;
    int m0 = mt * 64;
    if (m0 >= ne) return;

    uint32_t sb = smem_u32(smem);
    int tid = threadIdx.x;
    int lane = tid & 31, warp = tid >> 5;
    int wm = warp >> 2, wn = warp & 3;

    int* rowid = (int*)(smem + 3 * FC1_STG);
    if (tid < 64) {
        int mi = m0 + tid;
        rowid[tid] = g_rows_sorted[pb + (mi < ne ? mi : ne - 1)];
    }
    __syncthreads();

    int ar0 = tid >> 2, as0 = tid & 3;
    const char* ap0 = (const char*)g_obs_h + (size_t)rowid[ar0] * 2048 + as0 * 16;
    int bkp = tid >> 5, bns = tid & 31;
    const char* bp = (const char*)g_w1p +
                     (((size_t)e << 20) + nt * 128 + bns * 4) * 4;

    auto issue = [&](int st, int ch) {
        uint32_t s0 = sb + st * FC1_STG;
        cp_async16(s0 + ar0 * 80 + as0 * 16, ap0 + ch * 64);
        uint32_t sB = s0 + FC1_ASTAGE + bns * 16;
        cp_async16(sB + bkp * 544, bp + (size_t)(ch * 16 + bkp) * 8192);
        cp_async16(sB + (bkp + 8) * 544, bp + (size_t)(ch * 16 + bkp + 8) * 8192);
        cp_commit();
    };

    float c[2][4][4];
#pragma unroll
    for (int i = 0; i < 2; i++)
#pragma unroll
        for (int j = 0; j < 4; j++)
#pragma unroll
            for (int q = 0; q < 4; q++) c[i][j][q] = 0.f;

    issue(0, 0);
    issue(1, 1);

    uint32_t aoff = (uint32_t)(wm * 32 + (lane & 15)) * 80 + (lane >> 4) * 16;
    int colb = wn * 32 + (lane >> 2);
    int krow = lane & 3;

    for (int ch = 0; ch < 32; ch++) {
        if (ch < 31) cp_wait<1>(); else cp_wait<0>();
        __syncthreads();
        if (ch + 2 < 32) issue((ch + 2) % 3, ch + 2);

        uint32_t stg = sb + (ch % 3) * FC1_STG;
        const unsigned* Bp = (const unsigned*)(smem + (ch % 3) * FC1_STG + FC1_ASTAGE);

#pragma unroll
        for (int s = 0; s < 2; s++) {
            unsigned a[2][4];
#pragma unroll
            for (int i = 0; i < 2; i++)
                ldmatrix_x4(a[i], stg + aoff + i * 1280 + s * 32);
            unsigned b[4][2];
#pragma unroll
            for (int j = 0; j < 4; j++) {
                int w0 = (s * 8 + krow) * 136 + colb + j * 8;
                b[j][0] = Bp[w0];
                b[j][1] = Bp[w0 + 544];
            }
#pragma unroll
            for (int i = 0; i < 2; i++)
#pragma unroll
                for (int j = 0; j < 4; j++)
                    mma_f16(c[i][j], a[i][0], a[i][1], a[i][2], a[i][3], b[j][0], b[j][1]);
        }
    }

    const float* b1e = b1 + e * H_DIM + nt * 128;
#pragma unroll
    for (int i = 0; i < 2; i++) {
        int r0 = m0 + wm * 32 + i * 16 + (lane >> 2);
#pragma unroll
        for (int j = 0; j < 4; j++) {
            int cc = wn * 32 + j * 8 + 2 * (lane & 3);
            float bv0 = b1e[cc], bv1 = b1e[cc + 1];
            if (r0 < ne) {
                float y0 = fmaxf(c[i][j][0] + bv0, 0.f);
                float y1 = fmaxf(c[i][j][1] + bv1, 0.f);
                g_h[((size_t)(pb + r0) * H_DIM + nt * 128 + cc) >> 1] = pack_f16x2(y0, y1);
            }
            if (r0 + 8 < ne) {
                float y0 = fmaxf(c[i][j][2] + bv0, 0.f);
                float y1 = fmaxf(c[i][j][3] + bv1, 0.f);
                g_h[((size_t)(pb + r0 + 8) * H_DIM + nt * 128 + cc) >> 1] = pack_f16x2(y0, y1);
            }
        }
    }
}

__device__ __forceinline__ void action_body(int o, const float* __restrict__ obs,
                                            const float* __restrict__ lastw,
                                            const float* __restrict__ lastb,
                                            float* __restrict__ out, char* smem) {
    int tid = threadIdx.x;
    float* obsS = (float*)smem;                  // 1024 floats
    float* red  = obsS + D_DIM;                  // 16*64 floats
    float* muS  = red + 16 * A_DIM;              // 64
    float* eS   = muS + A_DIM;                   // 64

    obsS[tid]       = obs[(size_t)o * D_DIM + tid];
    obsS[tid + 256] = obs[(size_t)o * D_DIM + tid + 256];
    obsS[tid + 512] = obs[(size_t)o * D_DIM + tid + 512];
    obsS[tid + 768] = obs[(size_t)o * D_DIM + tid + 768];
    __syncthreads();

    int a4 = (tid & 15) * 4;
    int chunk = tid >> 4;                        // 0..15, 64 d each

    const float* lw = lastw + (size_t)o * D_DIM * A_DIM + (size_t)chunk * 64 * A_DIM + a4;
    float ax = 0.f, ay = 0.f, az = 0.f, aw = 0.f;
#pragma unroll 8
    for (int d = 0; d < 64; d++) {
        float4 w = *reinterpret_cast<const float4*>(lw + (size_t)d * A_DIM);
        float x = obsS[chunk * 64 + d];
        ax += x * w.x; ay += x * w.y; az += x * w.z; aw += x * w.w;
    }
    red[chunk * A_DIM + a4 + 0] = ax;
    red[chunk * A_DIM + a4 + 1] = ay;
    red[chunk * A_DIM + a4 + 2] = az;
    red[chunk * A_DIM + a4 + 3] = aw;
    __syncthreads();

    if (tid < A_DIM) {
        float m = 0.f;
        for (int c = 0; c < 16; c++) m += red[c * A_DIM + tid];
        muS[tid] = m + lastb[o * A_DIM + tid];
    }
    __syncthreads();
    if (tid < A_DIM) {
        float mx = muS[0];
        for (int i = 1; i < A_DIM; i++) mx = fmaxf(mx, muS[i]);
        float t  = muS[tid] - mx;
        float ef = expf(t);
        if (ef < FLT_MIN_NORM) ef = 0.f;         // FTZ emulation
        eS[tid] = ef;
    }
    __syncthreads();
    if (tid < A_DIM) {
        float ssum = 0.f;
        for (int i = 0; i < A_DIM; i++) ssum += eS[i];
        float p = eS[tid] / ssum;
        if (p < FLT_MIN_NORM) p = 0.f;           // FTZ emulation
        out[(size_t)o * A_DIM + tid] = p;
        float lp = (p == 0.f) ? logf(1e-8f) : logf(p);
        out[(size_t)O_DIM * A_DIM + o * A_DIM + tid] = lp;
    }
}

__device__ __forceinline__ void loss_body(float* __restrict__ out, char* smem) {
    int tid = threadIdx.x;
    float* sh = (float*)smem;                    // 9 floats used
    float imp[4], ld[4];
#pragma unroll
    for (int q = 0; q < 4; q++) {
        imp[q] = g_importance[tid + q * 256];
        ld[q]  = g_load[tid + q * 256];
    }
    auto reduceSum = [&](float v) -> float {
#pragma unroll
        for (int o2 = 16; o2; o2 >>= 1) v += __shfl_xor_sync(0xffffffffu, v, o2);
        if ((tid & 31) == 0) sh[tid >> 5] = v;
        __syncthreads();
        if (tid < 32) {
            float r = (tid < 8) ? sh[tid] : 0.f;
#pragma unroll
            for (int o2 = 4; o2; o2 >>= 1) r += __shfl_xor_sync(0xffffffffu, r, o2);
            if (tid == 0) sh[8] = r;
        }
        __syncthreads();
        float r = sh[8];
        __syncthreads();
        return r;
    };

    float si = reduceSum(imp[0] + imp[1] + imp[2] + imp[3]);
    float mi = si / (float)O_DIM;
    float di = 0.f;
#pragma unroll
    for (int q = 0; q < 4; q++) { float d = imp[q] - mi; di += d * d; }
    float ssi = reduceSum(di);
    float sl = reduceSum(ld[0] + ld[1] + ld[2] + ld[3]);
    float ml = sl / (float)O_DIM;
    float dl = 0.f;
#pragma unroll
    for (int q = 0; q < 4; q++) { float d = ld[q] - ml; dl += d * d; }
    float ssl = reduceSum(dl);
    if (tid == 0) {
        float vi = ssi / (float)(O_DIM - 1);
        float vl = ssl / (float)(O_DIM - 1);
        float loss = (vi / (mi * mi + 1e-10f) + vl / (ml * ml + 1e-10f)) * 0.01f;
        out[3 * O_DIM * A_DIM] = loss;
    }
}

__global__ __launch_bounds__(256, 3) void mega_kernel(const float* __restrict__ b1,
                                                      const float* __restrict__ obs,
                                                      const float* __restrict__ lastw,
                                                      const float* __restrict__ lastb,
                                                      float* __restrict__ out) {
    extern __shared__ char smem[];
    int bid = blockIdx.x;
    if (bid == MEGA_GRID - 1) { loss_body(out, smem); return; }
    if (bid % 5 == 0) { action_body(bid / 5, obs, lastw, lastb, out, smem); return; }
    fc1_body(bid - bid / 5 - 1, b1, smem);
}

// ---------------- fc2 grouped GEMM (fp16, ldmatrix, K-split 4) -------------
#define FC2_ASTAGE 5120
#define FC2_BSTAGE 4608
#define FC2_STG    (FC2_ASTAGE + FC2_BSTAGE)
#define FC2_SMEM   (3 * FC2_STG)

__global__ __launch_bounds__(256) void expert_fc2_kernel() {
    int ks = blockIdx.x, mt = blockIdx.y, e = blockIdx.z;
    int pb = g_base[e];
    int ne = g_base[e + 1] - pb;
    int m0 = mt * 64;
    if (m0 >= ne) return;
    int kp0 = ks * 256;

    extern __shared__ char smem[];
    uint32_t sb = smem_u32(smem);
    int tid = threadIdx.x;
    int lane = tid & 31, warp = tid >> 5;
    int wm = warp >> 2, wn = warp & 3;

    int ar = tid >> 2, as = tid & 3;
    int rowc = pb + m0 + ar;
    if (rowc > NPAIR - 1) rowc = NPAIR - 1;
    const char* ap = (const char*)g_h + (size_t)rowc * 4096 + kp0 * 4 + as * 16;
    int bkp = tid >> 4, bns = tid & 15;
    const char* bp = (const char*)g_w2p +
                     (((size_t)e << 16) + (size_t)(kp0 + bkp) * 64 + bns * 4) * 4;

    auto issue = [&](int st, int ch) {
        uint32_t s0 = sb + st * FC2_STG;
        cp_async16(s0 + ar * 80 + as * 16, ap + ch * 64);
        cp_async16(s0 + FC2_ASTAGE + bkp * 288 + bns * 16, bp + (size_t)ch * 16 * 256);
        cp_commit();
    };

    float c[2][2][4];
#pragma unroll
    for (int i = 0; i < 2; i++)
#pragma unroll
        for (int j = 0; j < 2; j++)
#pragma unroll
            for (int q = 0; q < 4; q++) c[i][j][q] = 0.f;

    issue(0, 0);
    issue(1, 1);

    uint32_t aoff = (uint32_t)(wm * 32 + (lane & 15)) * 80 + (lane >> 4) * 16;
    int colb = wn * 16 + (lane >> 2);
    int krow = lane & 3;

    for (int ch = 0; ch < 16; ch++) {
        if (ch < 15) cp_wait<1>(); else cp_wait<0>();
        __syncthreads();
        if (ch + 2 < 16) issue((ch + 2) % 3, ch + 2);

        uint32_t stg = sb + (ch % 3) * FC2_STG;
        const unsigned* Bp = (const unsigned*)(smem + (ch % 3) * FC2_STG + FC2_ASTAGE);

#pragma unroll
        for (int s = 0; s < 2; s++) {
            unsigned a[2][4];
#pragma unroll
            for (int i = 0; i < 2; i++)
                ldmatrix_x4(a[i], stg + aoff + i * 1280 + s * 32);
            unsigned b[2][2];
#pragma unroll
            for (int j = 0; j < 2; j++) {
                int w0 = (s * 8 + krow) * 72 + colb + j * 8;
                b[j][0] = Bp[w0];
                b[j][1] = Bp[w0 + 288];
            }
#pragma unroll
            for (int i = 0; i < 2; i++)
#pragma unroll
                for (int j = 0; j < 2; j++)
                    mma_f16(c[i][j], a[i][0], a[i][1], a[i][2], a[i][3], b[j][0], b[j][1]);
        }
    }

    float* zp = g_z + (size_t)ks * NPAIR * A_DIM;
#pragma unroll
    for (int i = 0; i < 2; i++) {
        int r0 = m0 + wm * 32 + i * 16 + (lane >> 2);
#pragma unroll
        for (int j = 0; j < 2; j++) {
            int c0 = wn * 16 + j * 8 + 2 * (lane & 3);
            if (r0 < ne) {
                float* dst = zp + (size_t)(pb + r0) * A_DIM + c0;
                dst[0] = c[i][j][0];
                dst[1] = c[i][j][1];
            }
            if (r0 + 8 < ne) {
                float* dst = zp + (size_t)(pb + r0 + 8) * A_DIM + c0;
                dst[0] = c[i][j][2];
                dst[1] = c[i][j][3];
            }
        }
    }
}

// ---------------- combine (sums 4 k-slice partials) ----------------
__global__ __launch_bounds__(256) void combine_kernel(const float* __restrict__ b2,
                                                      float* __restrict__ out) {
    int i = blockIdx.x * blockDim.x + threadIdx.x;
    if (i >= O_DIM * A_DIM) return;
    int o = i >> 6, a = i & 63;
    float y = 0.f;
#pragma unroll
    for (int j = 0; j < TOPK; j++) {
        int eidx = g_topk_idx[o * TOPK + j];
        float g  = g_topk_gate[o * TOPK + j];
        int p    = g_pair_of[o * TOPK + j];
        size_t base = (size_t)p * A_DIM + a;
        float z = g_z[base] + g_z[base + (size_t)NPAIR * A_DIM] +
                  g_z[base + 2 * (size_t)NPAIR * A_DIM] + g_z[base + 3 * (size_t)NPAIR * A_DIM];
        y += g * (z + b2[eidx * A_DIM + a]);
    }
    out[2 * O_DIM * A_DIM + i] = y;
}

// ---------------- launch ----------------------------------------------------
extern "C" void kernel_launch(void* const* d_in, const int* in_sizes, int n_in,
                              void* d_out, int out_size) {
    const float* obs   = (const float*)d_in[0];
    const float* wgate = (const float*)d_in[1];
    const float* w1    = (const float*)d_in[2];
    const float* b1    = (const float*)d_in[3];
    const float* w2    = (const float*)d_in[4];
    const float* b2    = (const float*)d_in[5];
    const float* lastw = (const float*)d_in[6];
    const float* lastb = (const float*)d_in[7];
    float* out = (float*)d_out;

    static int smem_set = 0;
    if (!smem_set) {
        cudaFuncSetAttribute(mega_kernel,
                             cudaFuncAttributeMaxDynamicSharedMemorySize, FC1_SMEM);
        cudaFuncSetAttribute(expert_fc2_kernel,
                             cudaFuncAttributeMaxDynamicSharedMemorySize, FC2_SMEM);
        smem_set = 1;
    }

    prep_gate_kernel<<<O_DIM + PREP_BLOCKS, 256>>>(obs, wgate, w1, w2);
    bin_kernel<<<1, 512>>>();
    mega_kernel<<<MEGA_GRID, 256, FC1_SMEM>>>(b1, obs, lastw, lastb, out);
    expert_fc2_kernel<<<dim3(4, 8, 16), 256, FC2_SMEM>>>();
    combine_kernel<<<(O_DIM * A_DIM + 255) / 256, 256>>>(b2, out);
}

// round 12
// speedup vs baseline: 2.6057x; 1.0209x over previous
#include <cuda_runtime.h>
#include <cuda_bf16.h>
#include <math.h>
#include <stdint.h>

#define O_DIM 1024
#define D_DIM 1024
#define E_NUM 16
#define TOPK  4
#define H_DIM 2048
#define A_DIM 64
#define NPAIR (O_DIM * TOPK)
#define FLT_MIN_NORM 1.17549435e-38f
#define MAXTILE 80

// ---------------- scratch (static device memory; no allocs) ----------------
__device__ int      g_topk_idx[NPAIR];
__device__ float    g_topk_gate[NPAIR];
__device__ float    g_importance[O_DIM];
__device__ float    g_load[O_DIM];
__device__ int      g_base[E_NUM + 1];
__device__ int      g_rows_sorted[NPAIR];
__device__ int      g_pair_of[NPAIR];
__device__ int      g_ntile;
__device__ int      g_tile_e[MAXTILE];
__device__ int      g_tile_m0[MAXTILE];
__device__ unsigned g_obs_h[O_DIM * D_DIM / 2];
__device__ unsigned g_w1p[E_NUM * (D_DIM / 2) * H_DIM];
__device__ unsigned g_w2p[E_NUM * (H_DIM / 2) * A_DIM];
__device__ unsigned g_h[NPAIR * H_DIM / 2];
__device__ float    g_z[4 * NPAIR * A_DIM];

#define N_OBS4 (O_DIM * D_DIM / 8)
#define N_W14  (E_NUM * (D_DIM / 2) * H_DIM / 4)
#define N_W24  (E_NUM * (H_DIM / 2) * A_DIM / 4)
#define PREP_BLOCKS ((N_OBS4 + N_W14 + N_W24) / 256)   // 17920

// ---------------- helpers ----------------
__device__ __forceinline__ uint32_t smem_u32(const void* p) {
    uint32_t a;
    asm("{ .reg .u64 t; cvta.to.shared.u64 t, %1; cvt.u32.u64 %0, t; }" : "=r"(a) : "l"(p));
    return a;
}
__device__ __forceinline__ void cp_async16(uint32_t saddr, const void* gptr) {
    asm volatile("cp.async.cg.shared.global [%0], [%1], 16;" :: "r"(saddr), "l"(gptr));
}
__device__ __forceinline__ void cp_commit() {
    asm volatile("cp.async.commit_group;" ::: "memory");
}
template <int N> __device__ __forceinline__ void cp_wait() {
    asm volatile("cp.async.wait_group %0;" :: "n"(N) : "memory");
}
__device__ __forceinline__ unsigned pack_f16x2(float lo, float hi) {
    unsigned u;
    asm("cvt.rn.f16x2.f32 %0, %1, %2;" : "=r"(u) : "f"(hi), "f"(lo));
    return u;
}
__device__ __forceinline__ void ldmatrix_x4(unsigned r[4], uint32_t saddr) {
    asm volatile("ldmatrix.sync.aligned.m8n8.x4.shared.b16 {%0,%1,%2,%3}, [%4];"
                 : "=r"(r[0]), "=r"(r[1]), "=r"(r[2]), "=r"(r[3]) : "r"(saddr));
}
__device__ __forceinline__ void mma_f16(float c[4], unsigned a0, unsigned a1,
                                        unsigned a2, unsigned a3,
                                        unsigned b0, unsigned b1) {
    asm volatile(
        "mma.sync.aligned.m16n8k16.row.col.f32.f16.f16.f32 "
        "{%0,%1,%2,%3}, {%4,%5,%6,%7}, {%8,%9}, {%0,%1,%2,%3};\n"
        : "+f"(c[0]), "+f"(c[1]), "+f"(c[2]), "+f"(c[3])
        : "r"(a0), "r"(a1), "r"(a2), "r"(a3), "r"(b0), "r"(b1));
}

// ============ fused kernel 1: gate (blocks 0..1023) + prep (rest) ==========
__global__ __launch_bounds__(256) void prep_gate_kernel(const float* __restrict__ obs,
                                                        const float* __restrict__ wg,
                                                        const float* __restrict__ w1,
                                                        const float* __restrict__ w2) {
    int bid = blockIdx.x;
    int tid = threadIdx.x;

    if (bid < O_DIM) {
        int o = bid;
        const float* wrow = wg + (size_t)o * D_DIM * E_NUM;
        const float* orow = obs + (size_t)o * D_DIM;

        float acc[E_NUM];
#pragma unroll
        for (int i = 0; i < E_NUM; i++) acc[i] = 0.f;
        for (int d = tid; d < D_DIM; d += 256) {
            float x = orow[d];
            const float4* p = reinterpret_cast<const float4*>(wrow + (size_t)d * E_NUM);
            float4 v0 = p[0], v1 = p[1], v2 = p[2], v3 = p[3];
            acc[0]  += x * v0.x; acc[1]  += x * v0.y; acc[2]  += x * v0.z; acc[3]  += x * v0.w;
            acc[4]  += x * v1.x; acc[5]  += x * v1.y; acc[6]  += x * v1.z; acc[7]  += x * v1.w;
            acc[8]  += x * v2.x; acc[9]  += x * v2.y; acc[10] += x * v2.z; acc[11] += x * v2.w;
            acc[12] += x * v3.x; acc[13] += x * v3.y; acc[14] += x * v3.z; acc[15] += x * v3.w;
        }
#pragma unroll
        for (int i = 0; i < E_NUM; i++) {
#pragma unroll
            for (int off = 16; off; off >>= 1)
                acc[i] += __shfl_xor_sync(0xffffffffu, acc[i], off);
        }
        __shared__ float s[8][E_NUM];
        int warp = tid >> 5, lane = tid & 31;
        if (lane == 0) {
#pragma unroll
            for (int i = 0; i < E_NUM; i++) s[warp][i] = acc[i];
        }
        __syncthreads();
        if (tid == 0) {
            float logit[E_NUM];
            for (int e = 0; e < E_NUM; e++) {
                float t = 0.f;
                for (int w = 0; w < 8; w++) t += s[w][e];
                logit[e] = t;
            }
            bool taken[E_NUM];
            for (int e = 0; e < E_NUM; e++) taken[e] = false;
            int idx[TOPK]; float val[TOPK];
            for (int k = 0; k < TOPK; k++) {
                float best = -3.4e38f; int bi = 0;
                for (int e = 0; e < E_NUM; e++)
                    if (!taken[e] && logit[e] > best) { best = logit[e]; bi = e; }
                taken[bi] = true; idx[k] = bi; val[k] = best;
            }
            float m = val[0];
            float ex[TOPK]; float se = 0.f;
            for (int k = 0; k < TOPK; k++) { ex[k] = expf(val[k] - m); se += ex[k]; }
            float gates[E_NUM];
            for (int e = 0; e < E_NUM; e++) gates[e] = 0.f;
            for (int k = 0; k < TOPK; k++) gates[idx[k]] = ex[k] / se;
            float imp = 0.f; int ldc = 0;
            for (int e = 0; e < E_NUM; e++) { imp += gates[e]; ldc += (gates[e] > 0.f); }
            for (int k = 0; k < TOPK; k++) {
                g_topk_idx[o * TOPK + k]  = idx[k];
                g_topk_gate[o * TOPK + k] = gates[idx[k]];
            }
            g_importance[o] = imp;
            g_load[o] = (float)ldc;
        }
        return;
    }

    int idx = (bid - O_DIM) * 256 + tid;
    if (idx < N_OBS4) {
        const float4* p = reinterpret_cast<const float4*>(obs) + idx * 2;
        float4 f0 = p[0], f1 = p[1];
        uint4 u;
        u.x = pack_f16x2(f0.x, f0.y);
        u.y = pack_f16x2(f0.z, f0.w);
        u.z = pack_f16x2(f1.x, f1.y);
        u.w = pack_f16x2(f1.z, f1.w);
        reinterpret_cast<uint4*>(g_obs_h)[idx] = u;
    } else if (idx < N_OBS4 + N_W14) {
        int t = idx - N_OBS4;
        int e  = t >> 18;
        int r  = t & 262143;
        int kp = r >> 9;
        int n4 = (r & 511) * 4;
        const float* p = w1 + ((size_t)e << 21) + ((size_t)kp << 12) + n4;
        float4 f0 = *reinterpret_cast<const float4*>(p);
        float4 f1 = *reinterpret_cast<const float4*>(p + 2048);
        uint4 u;
        u.x = pack_f16x2(f0.x, f1.x);
        u.y = pack_f16x2(f0.y, f1.y);
        u.z = pack_f16x2(f0.z, f1.z);
        u.w = pack_f16x2(f0.w, f1.w);
        *reinterpret_cast<uint4*>(g_w1p + ((size_t)e << 20) + (kp << 11) + n4) = u;
    } else if (idx < N_OBS4 + N_W14 + N_W24) {
        int t = idx - (N_OBS4 + N_W14);
        int e  = t >> 14;
        int r  = t & 16383;
        int kp = r >> 4;
        int n4 = (r & 15) * 4;
        const float* p = w2 + ((size_t)e << 17) + (kp << 7) + n4;
        float4 f0 = *reinterpret_cast<const float4*>(p);
        float4 f1 = *reinterpret_cast<const float4*>(p + 64);
        uint4 u;
        u.x = pack_f16x2(f0.x, f1.x);
        u.y = pack_f16x2(f0.y, f1.y);
        u.z = pack_f16x2(f0.z, f1.z);
        u.w = pack_f16x2(f0.w, f1.w);
        *reinterpret_cast<uint4*>(g_w2p + ((size_t)e << 16) + (kp << 6) + n4) = u;
    }
}

// ---------------- K2: binning + tile table ----------------
__global__ __launch_bounds__(512) void bin_kernel() {
    int tid = threadIdx.x;
    int warp = tid >> 5, lane = tid & 31;
    int e = warp;
    __shared__ int scnt[E_NUM];
    __shared__ int sbase[E_NUM + 1];

    int cnt = 0;
    for (int base = 0; base < O_DIM; base += 32) {
        int r = base + lane;
        bool f = (g_topk_idx[r * 4 + 0] == e) || (g_topk_idx[r * 4 + 1] == e) ||
                 (g_topk_idx[r * 4 + 2] == e) || (g_topk_idx[r * 4 + 3] == e);
        unsigned m = __ballot_sync(0xffffffffu, f);
        cnt += __popc(m);
    }
    if (lane == 0) scnt[e] = cnt;
    __syncthreads();
    if (tid == 0) {
        int s = 0;
        for (int q = 0; q < E_NUM; q++) { sbase[q] = s; s += scnt[q]; }
        sbase[E_NUM] = s;
        // compacted (expert, m0) tile table for fc1/fc2
        int t = 0;
        for (int q = 0; q < E_NUM; q++)
            for (int m0 = 0; m0 < scnt[q]; m0 += 64) {
                g_tile_e[t] = q;
                g_tile_m0[t] = m0;
                t++;
            }
        g_ntile = t;
    }
    __syncthreads();
    if (tid < E_NUM + 1) g_base[tid] = sbase[tid];

    int off = sbase[e];
    for (int base = 0; base < O_DIM; base += 32) {
        int r = base + lane;
        int j = -1;
        if      (g_topk_idx[r * 4 + 0] == e) j = 0;
        else if (g_topk_idx[r * 4 + 1] == e) j = 1;
        else if (g_topk_idx[r * 4 + 2] == e) j = 2;
        else if (g_topk_idx[r * 4 + 3] == e) j = 3;
        bool f = (j >= 0);
        unsigned m = __ballot_sync(0xffffffffu, f);
        int pos = off + __popc(m & ((1u << lane) - 1u));
        if (f) {
            g_rows_sorted[pos] = r;
            g_pair_of[r * 4 + j] = pos;
        }
        off += __popc(m);
    }
}

// ============ fused kernel 2: fc1 + action + loss in one grid ==============
#define FC1_ASTAGE 5120
#define FC1_BSTAGE 8704
#define FC1_STG    (FC1_ASTAGE + FC1_BSTAGE)
#define FC1_SMEM   (3 * FC1_STG + 256)
#define MEGA_GRID  (2305)   // 256*9 fc1/action groups + 1 loss

__device__ __forceinline__ void fc1_body(int nt, int tidx, const float* __restrict__ b1,
                                         char* smem) {
    if (tidx >= g_ntile) return;
    int e  = g_tile_e[tidx];
    int m0 = g_tile_m0[tidx];
    int pb = g_base[e];
    int ne = g_base[e + 1] - pb;

    uint32_t sb = smem_u32(smem);
    int tid = threadIdx.x;
    int lane = tid & 31, warp = tid >> 5;
    int wm = warp >> 2, wn = warp & 3;

    int* rowid = (int*)(smem + 3 * FC1_STG);
    if (tid < 64) {
        int mi = m0 + tid;
        rowid[tid] = g_rows_sorted[pb + (mi < ne ? mi : ne - 1)];
    }
    __syncthreads();

    int ar0 = tid >> 2, as0 = tid & 3;
    const char* ap0 = (const char*)g_obs_h + (size_t)rowid[ar0] * 2048 + as0 * 16;
    int bkp = tid >> 5, bns = tid & 31;
    const char* bp = (const char*)g_w1p +
                     (((size_t)e << 20) + nt * 128 + bns * 4) * 4;

    auto issue = [&](int st, int ch) {
        uint32_t s0 = sb + st * FC1_STG;
        cp_async16(s0 + ar0 * 80 + as0 * 16, ap0 + ch * 64);
        uint32_t sB = s0 + FC1_ASTAGE + bns * 16;
        cp_async16(sB + bkp * 544, bp + (size_t)(ch * 16 + bkp) * 8192);
        cp_async16(sB + (bkp + 8) * 544, bp + (size_t)(ch * 16 + bkp + 8) * 8192);
        cp_commit();
    };

    float c[2][4][4];
#pragma unroll
    for (int i = 0; i < 2; i++)
#pragma unroll
        for (int j = 0; j < 4; j++)
#pragma unroll
            for (int q = 0; q < 4; q++) c[i][j][q] = 0.f;

    issue(0, 0);
    issue(1, 1);

    uint32_t aoff = (uint32_t)(wm * 32 + (lane & 15)) * 80 + (lane >> 4) * 16;
    int colb = wn * 32 + (lane >> 2);
    int krow = lane & 3;

    for (int ch = 0; ch < 32; ch++) {
        if (ch < 31) cp_wait<1>(); else cp_wait<0>();
        __syncthreads();
        if (ch + 2 < 32) issue((ch + 2) % 3, ch + 2);

        uint32_t stg = sb + (ch % 3) * FC1_STG;
        const unsigned* Bp = (const unsigned*)(smem + (ch % 3) * FC1_STG + FC1_ASTAGE);

#pragma unroll
        for (int s = 0; s < 2; s++) {
            unsigned a[2][4];
#pragma unroll
            for (int i = 0; i < 2; i++)
                ldmatrix_x4(a[i], stg + aoff + i * 1280 + s * 32);
            unsigned b[4][2];
#pragma unroll
            for (int j = 0; j < 4; j++) {
                int w0 = (s * 8 + krow) * 136 + colb + j * 8;
                b[j][0] = Bp[w0];
                b[j][1] = Bp[w0 + 544];
            }
#pragma unroll
            for (int i = 0; i < 2; i++)
#pragma unroll
                for (int j = 0; j < 4; j++)
                    mma_f16(c[i][j], a[i][0], a[i][1], a[i][2], a[i][3], b[j][0], b[j][1]);
        }
    }

    const float* b1e = b1 + e * H_DIM + nt * 128;
#pragma unroll
    for (int i = 0; i < 2; i++) {
        int r0 = m0 + wm * 32 + i * 16 + (lane >> 2);
#pragma unroll
        for (int j = 0; j < 4; j++) {
            int cc = wn * 32 + j * 8 + 2 * (lane & 3);
            float bv0 = b1e[cc], bv1 = b1e[cc + 1];
            if (r0 < ne) {
                float y0 = fmaxf(c[i][j][0] + bv0, 0.f);
                float y1 = fmaxf(c[i][j][1] + bv1, 0.f);
                g_h[((size_t)(pb + r0) * H_DIM + nt * 128 + cc) >> 1] = pack_f16x2(y0, y1);
            }
            if (r0 + 8 < ne) {
                float y0 = fmaxf(c[i][j][2] + bv0, 0.f);
                float y1 = fmaxf(c[i][j][3] + bv1, 0.f);
                g_h[((size_t)(pb + r0 + 8) * H_DIM + nt * 128 + cc) >> 1] = pack_f16x2(y0, y1);
            }
        }
    }
}

__device__ __forceinline__ void action_body(int o, const float* __restrict__ obs,
                                            const float* __restrict__ lastw,
                                            const float* __restrict__ lastb,
                                            float* __restrict__ out, char* smem) {
    int tid = threadIdx.x;
    float* obsS = (float*)smem;
    float* red  = obsS + D_DIM;
    float* muS  = red + 16 * A_DIM;
    float* eS   = muS + A_DIM;

    obsS[tid]       = obs[(size_t)o * D_DIM + tid];
    obsS[tid + 256] = obs[(size_t)o * D_DIM + tid + 256];
    obsS[tid + 512] = obs[(size_t)o * D_DIM + tid + 512];
    obsS[tid + 768] = obs[(size_t)o * D_DIM + tid + 768];
    __syncthreads();

    int a4 = (tid & 15) * 4;
    int chunk = tid >> 4;

    const float* lw = lastw + (size_t)o * D_DIM * A_DIM + (size_t)chunk * 64 * A_DIM + a4;
    float ax = 0.f, ay = 0.f, az = 0.f, aw = 0.f;
#pragma unroll 8
    for (int d = 0; d < 64; d++) {
        float4 w = __ldcs(reinterpret_cast<const float4*>(lw + (size_t)d * A_DIM));
        float x = obsS[chunk * 64 + d];
        ax += x * w.x; ay += x * w.y; az += x * w.z; aw += x * w.w;
    }
    red[chunk * A_DIM + a4 + 0] = ax;
    red[chunk * A_DIM + a4 + 1] = ay;
    red[chunk * A_DIM + a4 + 2] = az;
    red[chunk * A_DIM + a4 + 3] = aw;
    __syncthreads();

    if (tid < A_DIM) {
        float m = 0.f;
        for (int c = 0; c < 16; c++) m += red[c * A_DIM + tid];
        muS[tid] = m + lastb[o * A_DIM + tid];
    }
    __syncthreads();
    if (tid < A_DIM) {
        float mx = muS[0];
        for (int i = 1; i < A_DIM; i++) mx = fmaxf(mx, muS[i]);
        float t  = muS[tid] - mx;
        float ef = expf(t);
        if (ef < FLT_MIN_NORM) ef = 0.f;         // FTZ emulation
        eS[tid] = ef;
    }
    __syncthreads();
    if (tid < A_DIM) {
        float ssum = 0.f;
        for (int i = 0; i < A_DIM; i++) ssum += eS[i];
        float p = eS[tid] / ssum;
        if (p < FLT_MIN_NORM) p = 0.f;           // FTZ emulation
        out[(size_t)o * A_DIM + tid] = p;
        float lp = (p == 0.f) ? logf(1e-8f) : logf(p);
        out[(size_t)O_DIM * A_DIM + o * A_DIM + tid] = lp;
    }
}

__device__ __forceinline__ void loss_body(float* __restrict__ out, char* smem) {
    int tid = threadIdx.x;
    float* sh = (float*)smem;
    float imp[4], ld[4];
#pragma unroll
    for (int q = 0; q < 4; q++) {
        imp[q] = g_importance[tid + q * 256];
        ld[q]  = g_load[tid + q * 256];
    }
    auto reduceSum = [&](float v) -> float {
#pragma unroll
        for (int o2 = 16; o2; o2 >>= 1) v += __shfl_xor_sync(0xffffffffu, v, o2);
        if ((tid & 31) == 0) sh[tid >> 5] = v;
        __syncthreads();
        if (tid < 32) {
            float r = (tid < 8) ? sh[tid] : 0.f;
#pragma unroll
            for (int o2 = 4; o2; o2 >>= 1) r += __shfl_xor_sync(0xffffffffu, r, o2);
            if (tid == 0) sh[8] = r;
        }
        __syncthreads();
        float r = sh[8];
        __syncthreads();
        return r;
    };

    float si = reduceSum(imp[0] + imp[1] + imp[2] + imp[3]);
    float mi = si / (float)O_DIM;
    float di = 0.f;
#pragma unroll
    for (int q = 0; q < 4; q++) { float d = imp[q] - mi; di += d * d; }
    float ssi = reduceSum(di);
    float sl = reduceSum(ld[0] + ld[1] + ld[2] + ld[3]);
    float ml = sl / (float)O_DIM;
    float dl = 0.f;
#pragma unroll
    for (int q = 0; q < 4; q++) { float d = ld[q] - ml; dl += d * d; }
    float ssl = reduceSum(dl);
    if (tid == 0) {
        float vi = ssi / (float)(O_DIM - 1);
        float vl = ssl / (float)(O_DIM - 1);
        float loss = (vi / (mi * mi + 1e-10f) + vl / (ml * ml + 1e-10f)) * 0.01f;
        out[3 * O_DIM * A_DIM] = loss;
    }
}

// grid 2305: groups of 9 blocks = 5 fc1 + 4 action; last block = loss.
__global__ __launch_bounds__(256, 3) void mega_kernel(const float* __restrict__ b1,
                                                      const float* __restrict__ obs,
                                                      const float* __restrict__ lastw,
                                                      const float* __restrict__ lastb,
                                                      float* __restrict__ out) {
    extern __shared__ char smem[];
    int bid = blockIdx.x;
    if (bid == MEGA_GRID - 1) { loss_body(out, smem); return; }
    int g = bid / 9, r = bid % 9;
    if (r < 5) {
        int fid = g * 5 + r;                     // 0..1279
        fc1_body(fid & 15, fid >> 4, b1, smem);  // nt, tile index
    } else {
        action_body(g * 4 + (r - 5), obs, lastw, lastb, out, smem);
    }
}

// ---------------- fc2 grouped GEMM (fp16, ldmatrix, K-split 4) -------------
#define FC2_ASTAGE 5120
#define FC2_BSTAGE 4608
#define FC2_STG    (FC2_ASTAGE + FC2_BSTAGE)
#define FC2_SMEM   (3 * FC2_STG)

__global__ __launch_bounds__(256) void expert_fc2_kernel() {
    int ks = blockIdx.x, tidx = blockIdx.y;
    if (tidx >= g_ntile) return;
    int e  = g_tile_e[tidx];
    int m0 = g_tile_m0[tidx];
    int pb = g_base[e];
    int ne = g_base[e + 1] - pb;
    int kp0 = ks * 256;

    extern __shared__ char smem[];
    uint32_t sb = smem_u32(smem);
    int tid = threadIdx.x;
    int lane = tid & 31, warp = tid >> 5;
    int wm = warp >> 2, wn = warp & 3;

    int ar = tid >> 2, as = tid & 3;
    int rowc = pb + m0 + ar;
    if (rowc > NPAIR - 1) rowc = NPAIR - 1;
    const char* ap = (const char*)g_h + (size_t)rowc * 4096 + kp0 * 4 + as * 16;
    int bkp = tid >> 4, bns = tid & 15;
    const char* bp = (const char*)g_w2p +
                     (((size_t)e << 16) + (size_t)(kp0 + bkp) * 64 + bns * 4) * 4;

    auto issue = [&](int st, int ch) {
        uint32_t s0 = sb + st * FC2_STG;
        cp_async16(s0 + ar * 80 + as * 16, ap + ch * 64);
        cp_async16(s0 + FC2_ASTAGE + bkp * 288 + bns * 16, bp + (size_t)ch * 16 * 256);
        cp_commit();
    };

    float c[2][2][4];
#pragma unroll
    for (int i = 0; i < 2; i++)
#pragma unroll
        for (int j = 0; j < 2; j++)
#pragma unroll
            for (int q = 0; q < 4; q++) c[i][j][q] = 0.f;

    issue(0, 0);
    issue(1, 1);

    uint32_t aoff = (uint32_t)(wm * 32 + (lane & 15)) * 80 + (lane >> 4) * 16;
    int colb = wn * 16 + (lane >> 2);
    int krow = lane & 3;

    for (int ch = 0; ch < 16; ch++) {
        if (ch < 15) cp_wait<1>(); else cp_wait<0>();
        __syncthreads();
        if (ch + 2 < 16) issue((ch + 2) % 3, ch + 2);

        uint32_t stg = sb + (ch % 3) * FC2_STG;
        const unsigned* Bp = (const unsigned*)(smem + (ch % 3) * FC2_STG + FC2_ASTAGE);

#pragma unroll
        for (int s = 0; s < 2; s++) {
            unsigned a[2][4];
#pragma unroll
            for (int i = 0; i < 2; i++)
                ldmatrix_x4(a[i], stg + aoff + i * 1280 + s * 32);
            unsigned b[2][2];
#pragma unroll
            for (int j = 0; j < 2; j++) {
                int w0 = (s * 8 + krow) * 72 + colb + j * 8;
                b[j][0] = Bp[w0];
                b[j][1] = Bp[w0 + 288];
            }
#pragma unroll
            for (int i = 0; i < 2; i++)
#pragma unroll
                for (int j = 0; j < 2; j++)
                    mma_f16(c[i][j], a[i][0], a[i][1], a[i][2], a[i][3], b[j][0], b[j][1]);
        }
    }

    float* zp = g_z + (size_t)ks * NPAIR * A_DIM;
#pragma unroll
    for (int i = 0; i < 2; i++) {
        int r0 = m0 + wm * 32 + i * 16 + (lane >> 2);
#pragma unroll
        for (int j = 0; j < 2; j++) {
            int c0 = wn * 16 + j * 8 + 2 * (lane & 3);
            if (r0 < ne) {
                float* dst = zp + (size_t)(pb + r0) * A_DIM + c0;
                dst[0] = c[i][j][0];
                dst[1] = c[i][j][1];
            }
            if (r0 + 8 < ne) {
                float* dst = zp + (size_t)(pb + r0 + 8) * A_DIM + c0;
                dst[0] = c[i][j][2];
                dst[1] = c[i][j][3];
            }
        }
    }
}

// ---------------- combine (sums 4 k-slice partials) ----------------
__global__ __launch_bounds__(256) void combine_kernel(const float* __restrict__ b2,
                                                      float* __restrict__ out) {
    int i = blockIdx.x * blockDim.x + threadIdx.x;
    if (i >= O_DIM * A_DIM) return;
    int o = i >> 6, a = i & 63;
    float y = 0.f;
#pragma unroll
    for (int j = 0; j < TOPK; j++) {
        int eidx = g_topk_idx[o * TOPK + j];
        float g  = g_topk_gate[o * TOPK + j];
        int p    = g_pair_of[o * TOPK + j];
        size_t base = (size_t)p * A_DIM + a;
        float z = g_z[base] + g_z[base + (size_t)NPAIR * A_DIM] +
                  g_z[base + 2 * (size_t)NPAIR * A_DIM] + g_z[base + 3 * (size_t)NPAIR * A_DIM];
        y += g * (z + b2[eidx * A_DIM + a]);
    }
    out[2 * O_DIM * A_DIM + i] = y;
}

// ---------------- launch ----------------------------------------------------
extern "C" void kernel_launch(void* const* d_in, const int* in_sizes, int n_in,
                              void* d_out, int out_size) {
    const float* obs   = (const float*)d_in[0];
    const float* wgate = (const float*)d_in[1];
    const float* w1    = (const float*)d_in[2];
    const float* b1    = (const float*)d_in[3];
    const float* w2    = (const float*)d_in[4];
    const float* b2    = (const float*)d_in[5];
    const float* lastw = (const float*)d_in[6];
    const float* lastb = (const float*)d_in[7];
    float* out = (float*)d_out;

    static int smem_set = 0;
    if (!smem_set) {
        cudaFuncSetAttribute(mega_kernel,
                             cudaFuncAttributeMaxDynamicSharedMemorySize, FC1_SMEM);
        cudaFuncSetAttribute(expert_fc2_kernel,
                             cudaFuncAttributeMaxDynamicSharedMemorySize, FC2_SMEM);
        smem_set = 1;
    }

    prep_gate_kernel<<<O_DIM + PREP_BLOCKS, 256>>>(obs, wgate, w1, w2);
    bin_kernel<<<1, 512>>>();
    mega_kernel<<<MEGA_GRID, 256, FC1_SMEM>>>(b1, obs, lastw, lastb, out);
    expert_fc2_kernel<<<dim3(4, MAXTILE), 256, FC2_SMEM>>>();
    combine_kernel<<<(O_DIM * A_DIM + 255) / 256, 256>>>(b2, out);
}